// round 12
// baseline (speedup 1.0000x reference)
#include <cuda_runtime.h>
#include <cuda_fp16.h>
#include <math.h>

#define NSEQ 256
#define CZ   128
#define NH   4
#define HD   32
#define RTOT (NSEQ * NSEQ)

typedef unsigned int u32;
typedef unsigned long long u64;

// ---------------- global scratch ----------------
__device__ __half g_Qh[(size_t)RTOT * CZ];   // pre-scaled
__device__ __half g_Kh[(size_t)RTOT * CZ];
__device__ __half g_Vh[(size_t)RTOT * CZ];
__device__ __half g_Gh[(size_t)RTOT * CZ];   // gate, fp16
__device__ __half g_BiasT[(size_t)NH * RTOT]; // fp16
__device__ __half g_AVh[(size_t)RTOT * CZ];
__device__ __half g_Wt[5][CZ * CZ];

// ---------------- helpers ----------------
__device__ __forceinline__ u32 smem_u32(const void* p) {
    u32 a;
    asm("{ .reg .u64 t; cvta.to.shared.u64 t, %1; cvt.u32.u64 %0, t; }" : "=r"(a) : "l"(p));
    return a;
}
__device__ __forceinline__ void ldsm_x4(u32* r, u32 addr) {
    asm volatile("ldmatrix.sync.aligned.m8n8.x4.shared.b16 {%0,%1,%2,%3}, [%4];"
        : "=r"(r[0]), "=r"(r[1]), "=r"(r[2]), "=r"(r[3]) : "r"(addr));
}
__device__ __forceinline__ void ldsm_x4_t(u32* r, u32 addr) {
    asm volatile("ldmatrix.sync.aligned.m8n8.x4.trans.shared.b16 {%0,%1,%2,%3}, [%4];"
        : "=r"(r[0]), "=r"(r[1]), "=r"(r[2]), "=r"(r[3]) : "r"(addr));
}
__device__ __forceinline__ void mma_f16(float* d, const u32* a, const u32* b) {
    asm volatile("mma.sync.aligned.m16n8k16.row.col.f32.f16.f16.f32 "
        "{%0,%1,%2,%3}, {%4,%5,%6,%7}, {%8,%9}, {%0,%1,%2,%3};"
        : "+f"(d[0]), "+f"(d[1]), "+f"(d[2]), "+f"(d[3])
        : "r"(a[0]), "r"(a[1]), "r"(a[2]), "r"(a[3]), "r"(b[0]), "r"(b[1]));
}
__device__ __forceinline__ u32 pack_h2(float x, float y) {
    __half2 t;
    t.x = __float2half_rn(x);
    t.y = __float2half_rn(y);
    return *(u32*)&t;
}
__device__ __forceinline__ float2 unpack_h2(u32 v) {
    __half2 t = *(__half2*)&v;
    return __half22float2(t);
}
__device__ __forceinline__ void cp16(u32 dst, const void* src) {
    u64 g;
    asm("cvta.to.global.u64 %0, %1;" : "=l"(g) : "l"(src));
    asm volatile("cp.async.ca.shared.global [%0], [%1], 16;" :: "r"(dst), "l"(g));
}
#define CP_COMMIT() asm volatile("cp.async.commit_group;")
#define CP_WAIT(n)  asm volatile("cp.async.wait_group %0;" :: "n"(n))

#define TSTRIDE 136
#define TBUF    34816

// lnproj smem: A (34816) | B buf0 | B buf1 | Wb; xs fp32 overlays SB0+SB1
#define LNP_SA   0
#define LNP_SB0  34816
#define LNP_SB1  69632
#define LNP_XS   34816
#define LNP_WB   104448
#define LNP_SMEM 106496
// outproj smem (128-row tiles)
#define OP_SA    0
#define OP_SB    34816
#define OP_SMEM  69632

// ---------------------------------------------------------------------------
// Kernel 0: transpose weights -> fp16
// ---------------------------------------------------------------------------
__global__ void wtransform(const float* __restrict__ Wq, const float* __restrict__ Wk,
                           const float* __restrict__ Wv, const float* __restrict__ Wg,
                           const float* __restrict__ Wo)
{
    const float* W = (blockIdx.x == 0) ? Wq : (blockIdx.x == 1) ? Wk :
                     (blockIdx.x == 2) ? Wv : (blockIdx.x == 3) ? Wg : Wo;
    __half* H = g_Wt[blockIdx.x];
    for (int e = threadIdx.x; e < CZ * CZ; e += blockDim.x) {
        int n = e >> 7, c = e & 127;
        H[e] = __float2half_rn(W[c * CZ + n]);
    }
}

// ---------------------------------------------------------------------------
// 64x32 warp-tile GEMM mainloop
// ---------------------------------------------------------------------------
__device__ __forceinline__ void gemm_warp64(float acc[16][4], u32 aBase, u32 bBase)
{
#pragma unroll
    for (int ks = 0; ks < 8; ks++) {
        u32 a0[4], a1[4], a2[4], a3[4], b0[4], b1[4];
        ldsm_x4(a0, aBase + ks * 32);
        ldsm_x4(a1, aBase + (u32)(16 * TSTRIDE) * 2 + ks * 32);
        ldsm_x4(a2, aBase + (u32)(32 * TSTRIDE) * 2 + ks * 32);
        ldsm_x4(a3, aBase + (u32)(48 * TSTRIDE) * 2 + ks * 32);
        ldsm_x4(b0, bBase + ks * 32);
        ldsm_x4(b1, bBase + (u32)(16 * TSTRIDE) * 2 + ks * 32);
        mma_f16(acc[0],  a0, b0); mma_f16(acc[1],  a0, b0 + 2);
        mma_f16(acc[2],  a0, b1); mma_f16(acc[3],  a0, b1 + 2);
        mma_f16(acc[4],  a1, b0); mma_f16(acc[5],  a1, b0 + 2);
        mma_f16(acc[6],  a1, b1); mma_f16(acc[7],  a1, b1 + 2);
        mma_f16(acc[8],  a2, b0); mma_f16(acc[9],  a2, b0 + 2);
        mma_f16(acc[10], a2, b1); mma_f16(acc[11], a2, b1 + 2);
        mma_f16(acc[12], a3, b0); mma_f16(acc[13], a3, b0 + 2);
        mma_f16(acc[14], a3, b1); mma_f16(acc[15], a3, b1 + 2);
    }
}

__device__ __forceinline__ void cp_weights(u32 sb, u32 bufOff, int m, int tid, int nthr)
{
    for (int e = tid; e < 2048; e += nthr) {
        int n = e >> 4, ch = e & 15;
        const __half* src = g_Wt[m] + n * 128 + ch * 8;
        cp16(sb + bufOff + (u32)(n * TSTRIDE + ch * 8) * 2, src);
    }
    CP_COMMIT();
}

// ---------------------------------------------------------------------------
// Kernel 1: LN + 4 projections (1-term) + bias projection (fp16 out)
// ---------------------------------------------------------------------------
__global__ __launch_bounds__(256, 2) void lnproj_mma(const float* __restrict__ x,
                                                     const float* __restrict__ gamma,
                                                     const float* __restrict__ beta,
                                                     const float* __restrict__ Wb,
                                                     const float* __restrict__ bg)
{
    extern __shared__ char sm[];
    const u32 sb = smem_u32(sm);
    const int tid = threadIdx.x, wid = tid >> 5, lane = tid & 31;
    const int wr = wid & 1, wc = wid >> 1;
    const size_t r0 = (size_t)blockIdx.x * 128;
    float* xs  = (float*)(sm + LNP_XS);
    float* sWb = (float*)(sm + LNP_WB);

    const float4* xg = (const float4*)(x + r0 * CZ);
    for (int i = tid; i < 4096; i += 256) {
        float4 v = xg[i];
        int row = i >> 5, c = (i & 31) << 2;
        float* d = xs + row * 129 + c;
        d[0] = v.x; d[1] = v.y; d[2] = v.z; d[3] = v.w;
    }
    sWb[tid] = Wb[tid];
    sWb[tid + 256] = Wb[tid + 256];
    __syncthreads();

    // LayerNorm: 2 threads per row
    {
        int row = tid >> 1, sub = tid & 1;
        float* rp = xs + row * 129;
        float s = 0.f, s2 = 0.f;
#pragma unroll
        for (int c = sub * 64; c < sub * 64 + 64; c++) { float v = rp[c]; s += v; s2 += v * v; }
        s  += __shfl_xor_sync(0xFFFFFFFF, s, 1);
        s2 += __shfl_xor_sync(0xFFFFFFFF, s2, 1);
        float mu  = s * (1.f / 128.f);
        float var = s2 * (1.f / 128.f) - mu * mu;
        float inv = rsqrtf(var + 1e-5f);
#pragma unroll
        for (int c = sub * 64; c < sub * 64 + 64; c++)
            rp[c] = (rp[c] - mu) * inv * __ldg(gamma + c) + __ldg(beta + c);
    }
    __syncthreads();

    // bias projection (fp32 math, fp16 store)
    for (int o = tid; o < 512; o += 256) {
        int row = o >> 2, h = o & 3;
        const float* xr = xs + row * 129;
        float s = 0.f;
#pragma unroll 8
        for (int c = 0; c < 128; c++) s += xr[c] * sWb[c * 4 + h];
        g_BiasT[(size_t)h * RTOT + r0 + row] = __float2half_rn(s);
    }
    // convert A -> fp16 in smem
    for (int p = tid; p < 8192; p += 256) {
        int row = p >> 6, c = (p & 63) << 1;
        u32 hh = pack_h2(xs[row * 129 + c], xs[row * 129 + c + 1]);
        *(u32*)(sm + LNP_SA + (u32)(row * TSTRIDE + c) * 2) = hh;
    }
    __syncthreads();

    cp_weights(sb, LNP_SB0, 0, tid, 256);

    const int i_ = lane >> 3, r_ = lane & 7;
    const u32 aBase = sb + LNP_SA +
        (u32)((wr * 64 + ((i_ & 1) << 3) + r_) * TSTRIDE + ((i_ >> 1) << 3)) * 2;
    const u32 bOffW = (u32)((wc * 32 + ((i_ >> 1) << 3) + r_) * TSTRIDE + ((i_ & 1) << 3)) * 2;
    const int g = lane >> 2, tig = lane & 3;

#pragma unroll
    for (int m = 0; m < 4; m++) {
        if (m < 3) cp_weights(sb, (m & 1) ? LNP_SB0 : LNP_SB1, m + 1, tid, 256);
        if (m < 3) { CP_WAIT(1); } else { CP_WAIT(0); }
        __syncthreads();

        const u32 bufOff = (m & 1) ? LNP_SB1 : LNP_SB0;
        float acc[16][4];
#pragma unroll
        for (int t = 0; t < 16; t++)
#pragma unroll
            for (int v = 0; v < 4; v++) acc[t][v] = 0.f;

        gemm_warp64(acc, aBase, sb + bufOff + bOffW);

        if (m == 0) {
            const float qs = 0.17677669529663689f;
#pragma unroll
            for (int ai = 0; ai < 4; ai++) {
                size_t rowA = r0 + wr * 64 + ai * 16 + g;
                size_t rowB = rowA + 8;
#pragma unroll
                for (int ni = 0; ni < 4; ni++) {
                    int col = wc * 32 + ni * 8 + tig * 2;
                    float* a = acc[ai * 4 + ni];
                    *(u32*)(g_Qh + rowA * CZ + col) = pack_h2(a[0] * qs, a[1] * qs);
                    *(u32*)(g_Qh + rowB * CZ + col) = pack_h2(a[2] * qs, a[3] * qs);
                }
            }
        } else if (m < 3) {
            __half* O = (m == 1) ? g_Kh : g_Vh;
#pragma unroll
            for (int ai = 0; ai < 4; ai++) {
                size_t rowA = r0 + wr * 64 + ai * 16 + g;
                size_t rowB = rowA + 8;
#pragma unroll
                for (int ni = 0; ni < 4; ni++) {
                    int col = wc * 32 + ni * 8 + tig * 2;
                    float* a = acc[ai * 4 + ni];
                    *(u32*)(O + rowA * CZ + col) = pack_h2(a[0], a[1]);
                    *(u32*)(O + rowB * CZ + col) = pack_h2(a[2], a[3]);
                }
            }
        } else {
#pragma unroll
            for (int ai = 0; ai < 4; ai++) {
                size_t rowA = r0 + wr * 64 + ai * 16 + g;
                size_t rowB = rowA + 8;
#pragma unroll
                for (int ni = 0; ni < 4; ni++) {
                    int col = wc * 32 + ni * 8 + tig * 2;
                    float2 bgv = __ldg((const float2*)(bg + col));
                    float* a = acc[ai * 4 + ni];
                    float gA0 = 1.f / (1.f + __expf(-(a[0] + bgv.x)));
                    float gA1 = 1.f / (1.f + __expf(-(a[1] + bgv.y)));
                    float gB0 = 1.f / (1.f + __expf(-(a[2] + bgv.x)));
                    float gB1 = 1.f / (1.f + __expf(-(a[3] + bgv.y)));
                    *(u32*)(g_Gh + rowA * CZ + col) = pack_h2(gA0, gA1);
                    *(u32*)(g_Gh + rowB * CZ + col) = pack_h2(gB0, gB1);
                }
            }
        }
        __syncthreads();
    }
}

// ---------------------------------------------------------------------------
// Kernel 2: attention. Grid (256, 4). 8 warps x 32 j. fp16 bias + gate.
// ---------------------------------------------------------------------------
#define KSTR 40
#define AT_BUF 20480
#define AT_SMEM (2 * AT_BUF)

__global__ __launch_bounds__(256, 2) void attn_mma()
{
    extern __shared__ char sm[];
    const u32 sb = smem_u32(sm);
    const int tid = threadIdx.x, wid = tid >> 5, lane = tid & 31;
    const int bi = blockIdx.x;
    const int h  = blockIdx.y;
    const size_t base = ((size_t)bi * NSEQ) * CZ + (size_t)h * HD;

    for (int e = tid; e < 2048; e += 256) {
        int buf = e >> 10, rem = e & 1023, k = rem >> 2, ch = rem & 3;
        const __half* src = ((buf == 0) ? g_Kh : g_Vh) + base + (size_t)k * CZ + ch * 8;
        cp16(sb + (u32)buf * AT_BUF + (u32)(k * KSTR + ch * 8) * 2, src);
    }
    CP_COMMIT();

    const int jr = wid * 32;
    const int r  = lane >> 2, c2 = (lane & 3) << 1;

    u32 qh[2][2][4];
#pragma unroll
    for (int a = 0; a < 2; a++)
#pragma unroll
        for (int ks = 0; ks < 2; ks++)
#pragma unroll
            for (int reg = 0; reg < 4; reg++) {
                int row = jr + a * 16 + r + (reg & 1) * 8;
                int col = ks * 16 + c2 + ((reg >> 1) << 3);
                qh[a][ks][reg] = *(const u32*)(g_Qh + base + (size_t)row * CZ + col);
            }

    CP_WAIT(0);
    __syncthreads();

    const int i_ = lane >> 3, r_ = lane & 7;
    const int brow = ((i_ >> 1) << 3) + r_;
    const int bcol = (i_ & 1) << 3;
    const int vsel = lane >> 3, vrow = lane & 7;
    const u32 vOff = (u32)(((vsel & 1) * 8 + vrow) * KSTR + ((vsel >> 1) << 3)) * 2;

    float oacc[2][4][4];
#pragma unroll
    for (int a = 0; a < 2; a++)
#pragma unroll
        for (int t = 0; t < 4; t++)
#pragma unroll
            for (int v = 0; v < 4; v++) oacc[a][t][v] = 0.f;
    float lsum[2][2] = {{0.f, 0.f}, {0.f, 0.f}};

    const __half* biasH = g_BiasT + (size_t)h * RTOT;

    for (int kc = 0; kc < 8; kc++) {
        float sacc[2][4][4];
#pragma unroll
        for (int a = 0; a < 2; a++)
#pragma unroll
            for (int t = 0; t < 4; t++)
#pragma unroll
                for (int v = 0; v < 4; v++) sacc[a][t][v] = 0.f;

        // ---- S = Q K^T over 32-k chunk ----
#pragma unroll
        for (int ks = 0; ks < 2; ks++) {
            u32 k0[4], k1[4];
            u32 ka = sb + (u32)((kc * 32 + brow) * KSTR + ks * 16 + bcol) * 2;
            ldsm_x4(k0, ka);
            ldsm_x4(k1, ka + (u32)(16 * KSTR) * 2);
#pragma unroll
            for (int a = 0; a < 2; a++) {
                mma_f16(sacc[a][0], qh[a][ks], k0);
                mma_f16(sacc[a][1], qh[a][ks], k0 + 2);
                mma_f16(sacc[a][2], qh[a][ks], k1);
                mma_f16(sacc[a][3], qh[a][ks], k1 + 2);
            }
        }

        // ---- bias (fp16) + exp ----
#pragma unroll
        for (int a = 0; a < 2; a++) {
            const __half* b0p = biasH + (size_t)(jr + a * 16 + r) * NSEQ;
            const __half* b1p = b0p + 8 * NSEQ;
#pragma unroll
            for (int nt = 0; nt < 4; nt++) {
                int kcol = kc * 32 + nt * 8 + c2;
                float2 b0 = unpack_h2(__ldg((const u32*)(b0p + kcol)));
                float2 b1 = unpack_h2(__ldg((const u32*)(b1p + kcol)));
                float p00 = __expf(sacc[a][nt][0] + b0.x);
                float p01 = __expf(sacc[a][nt][1] + b0.y);
                float p10 = __expf(sacc[a][nt][2] + b1.x);
                float p11 = __expf(sacc[a][nt][3] + b1.y);
                sacc[a][nt][0] = p00; sacc[a][nt][1] = p01;
                sacc[a][nt][2] = p10; sacc[a][nt][3] = p11;
                lsum[a][0] += p00 + p01;
                lsum[a][1] += p10 + p11;
            }
        }

        // ---- O += P V ----
#pragma unroll
        for (int ks2 = 0; ks2 < 2; ks2++) {
            u32 va = sb + AT_BUF + (u32)((kc * 32 + ks2 * 16) * KSTR) * 2 + vOff;
            u32 vh[8];
            ldsm_x4_t(vh,     va);
            ldsm_x4_t(vh + 4, va + 32);
#pragma unroll
            for (int a = 0; a < 2; a++) {
                u32 phi[4];
                const float* s0 = sacc[a][2 * ks2];
                const float* s1 = sacc[a][2 * ks2 + 1];
                phi[0] = pack_h2(s0[0], s0[1]);
                phi[1] = pack_h2(s0[2], s0[3]);
                phi[2] = pack_h2(s1[0], s1[1]);
                phi[3] = pack_h2(s1[2], s1[3]);
#pragma unroll
                for (int ntd = 0; ntd < 4; ntd++)
                    mma_f16(oacc[a][ntd], phi, vh + 2 * ntd);
            }
        }
    }

#pragma unroll
    for (int a = 0; a < 2; a++)
#pragma unroll
        for (int c = 0; c < 2; c++) {
            lsum[a][c] += __shfl_xor_sync(0xFFFFFFFF, lsum[a][c], 1);
            lsum[a][c] += __shfl_xor_sync(0xFFFFFFFF, lsum[a][c], 2);
        }

#pragma unroll
    for (int a = 0; a < 2; a++) {
        const float inv0 = __fdividef(1.f, lsum[a][0]);
        const float inv1 = __fdividef(1.f, lsum[a][1]);
        const size_t row0 = base + (size_t)(jr + a * 16 + r) * CZ;
        const size_t row1 = row0 + 8 * CZ;
#pragma unroll
        for (int ntd = 0; ntd < 4; ntd++) {
            int col = ntd * 8 + c2;
            float2 g0 = unpack_h2(__ldg((const u32*)(g_Gh + row0 + col)));
            float2 g1 = unpack_h2(__ldg((const u32*)(g_Gh + row1 + col)));
            *(u32*)(g_AVh + row0 + col) = pack_h2(oacc[a][ntd][0] * inv0 * g0.x,
                                                  oacc[a][ntd][1] * inv0 * g0.y);
            *(u32*)(g_AVh + row1 + col) = pack_h2(oacc[a][ntd][2] * inv1 * g1.x,
                                                  oacc[a][ntd][3] * inv1 * g1.y);
        }
    }
}

// ---------------------------------------------------------------------------
// Kernel 3: output projection, 128-row CTAs, 8 warps (64x32 tiles)
// ---------------------------------------------------------------------------
__global__ __launch_bounds__(256, 2) void outproj_mma(const float* __restrict__ bo_,
                                                      float* __restrict__ out)
{
    extern __shared__ char sm[];
    const u32 sb = smem_u32(sm);
    const int tid = threadIdx.x, wid = tid >> 5, lane = tid & 31;
    const int wr = wid & 1, wc = wid >> 1;
    const size_t r0 = (size_t)blockIdx.x * 128;

    for (int e = tid; e < 2048; e += 256) {
        int row = e >> 4, ch = e & 15;
        const __half* src = g_AVh + (r0 + row) * CZ + ch * 8;
        cp16(sb + OP_SA + (u32)(row * TSTRIDE + ch * 8) * 2, src);
    }
    CP_COMMIT();
    cp_weights(sb, OP_SB, 4, tid, 256);
    CP_WAIT(0);
    __syncthreads();

    const int i_ = lane >> 3, r_ = lane & 7;
    const u32 aBase = sb + OP_SA +
        (u32)((wr * 64 + ((i_ & 1) << 3) + r_) * TSTRIDE + ((i_ >> 1) << 3)) * 2;
    const u32 bBase = sb + OP_SB +
        (u32)((wc * 32 + ((i_ >> 1) << 3) + r_) * TSTRIDE + ((i_ & 1) << 3)) * 2;

    float acc[16][4];
#pragma unroll
    for (int t = 0; t < 16; t++)
#pragma unroll
        for (int v = 0; v < 4; v++) acc[t][v] = 0.f;

    gemm_warp64(acc, aBase, bBase);

    const int g = lane >> 2, tig = lane & 3;
#pragma unroll
    for (int ai = 0; ai < 4; ai++) {
        size_t rowA = r0 + wr * 64 + ai * 16 + g;
        size_t rowB = rowA + 8;
#pragma unroll
        for (int ni = 0; ni < 4; ni++) {
            int col = wc * 32 + ni * 8 + tig * 2;
            float2 bov = __ldg((const float2*)(bo_ + col));
            float* a = acc[ai * 4 + ni];
            *(float2*)(out + rowA * CZ + col) = make_float2(a[0] + bov.x, a[1] + bov.y);
            *(float2*)(out + rowB * CZ + col) = make_float2(a[2] + bov.x, a[3] + bov.y);
        }
    }
}

// ---------------------------------------------------------------------------
extern "C" void kernel_launch(void* const* d_in, const int* in_sizes, int n_in,
                              void* d_out, int out_size)
{
    const float* x     = (const float*)d_in[0];
    const float* gamma = (const float*)d_in[1];
    const float* beta  = (const float*)d_in[2];
    const float* Wq    = (const float*)d_in[3];
    const float* Wk    = (const float*)d_in[4];
    const float* Wv    = (const float*)d_in[5];
    const float* Wb    = (const float*)d_in[6];
    const float* Wg    = (const float*)d_in[7];
    const float* bg    = (const float*)d_in[8];
    const float* Wo    = (const float*)d_in[9];
    const float* bo    = (const float*)d_in[10];
    float* out = (float*)d_out;

    cudaFuncSetAttribute(lnproj_mma,  cudaFuncAttributeMaxDynamicSharedMemorySize, LNP_SMEM);
    cudaFuncSetAttribute(outproj_mma, cudaFuncAttributeMaxDynamicSharedMemorySize, OP_SMEM);
    cudaFuncSetAttribute(attn_mma,    cudaFuncAttributeMaxDynamicSharedMemorySize, AT_SMEM);

    wtransform<<<5, 256>>>(Wq, Wk, Wv, Wg, Wo);
    lnproj_mma<<<RTOT / 128, 256, LNP_SMEM>>>(x, gamma, beta, Wb, bg);
    dim3 g2(NSEQ, NH);
    attn_mma<<<g2, 256, AT_SMEM>>>();
    outproj_mma<<<RTOT / 128, 256, OP_SMEM>>>(bo, out);
}

// round 13
// speedup vs baseline: 1.0018x; 1.0018x over previous
#include <cuda_runtime.h>
#include <cuda_fp16.h>
#include <math.h>

#define NSEQ 256
#define CZ   128
#define NH   4
#define HD   32
#define RTOT (NSEQ * NSEQ)

typedef unsigned int u32;
typedef unsigned long long u64;

// ---------------- global scratch ----------------
__device__ __half g_Qh[(size_t)RTOT * CZ];    // pre-scaled by log2e/sqrt(32)
__device__ __half g_Kh[(size_t)RTOT * CZ];
__device__ __half g_Vh[(size_t)RTOT * CZ];
__device__ __half g_Gh[(size_t)RTOT * CZ];    // gate, fp16
__device__ __half g_BiasT[(size_t)NH * RTOT]; // fp16, pre-scaled by log2e
__device__ __half g_Wt[5][CZ * CZ];

// ---------------- helpers ----------------
__device__ __forceinline__ u32 smem_u32(const void* p) {
    u32 a;
    asm("{ .reg .u64 t; cvta.to.shared.u64 t, %1; cvt.u32.u64 %0, t; }" : "=r"(a) : "l"(p));
    return a;
}
__device__ __forceinline__ void ldsm_x4(u32* r, u32 addr) {
    asm volatile("ldmatrix.sync.aligned.m8n8.x4.shared.b16 {%0,%1,%2,%3}, [%4];"
        : "=r"(r[0]), "=r"(r[1]), "=r"(r[2]), "=r"(r[3]) : "r"(addr));
}
__device__ __forceinline__ void ldsm_x4_t(u32* r, u32 addr) {
    asm volatile("ldmatrix.sync.aligned.m8n8.x4.trans.shared.b16 {%0,%1,%2,%3}, [%4];"
        : "=r"(r[0]), "=r"(r[1]), "=r"(r[2]), "=r"(r[3]) : "r"(addr));
}
__device__ __forceinline__ void mma_f16(float* d, const u32* a, const u32* b) {
    asm volatile("mma.sync.aligned.m16n8k16.row.col.f32.f16.f16.f32 "
        "{%0,%1,%2,%3}, {%4,%5,%6,%7}, {%8,%9}, {%0,%1,%2,%3};"
        : "+f"(d[0]), "+f"(d[1]), "+f"(d[2]), "+f"(d[3])
        : "r"(a[0]), "r"(a[1]), "r"(a[2]), "r"(a[3]), "r"(b[0]), "r"(b[1]));
}
__device__ __forceinline__ u32 pack_h2(float x, float y) {
    __half2 t;
    t.x = __float2half_rn(x);
    t.y = __float2half_rn(y);
    return *(u32*)&t;
}
__device__ __forceinline__ float2 unpack_h2(u32 v) {
    __half2 t = *(__half2*)&v;
    return __half22float2(t);
}
__device__ __forceinline__ void cp16(u32 dst, const void* src) {
    u64 g;
    asm("cvta.to.global.u64 %0, %1;" : "=l"(g) : "l"(src));
    asm volatile("cp.async.ca.shared.global [%0], [%1], 16;" :: "r"(dst), "l"(g));
}
#define CP_COMMIT() asm volatile("cp.async.commit_group;")
#define CP_WAIT(n)  asm volatile("cp.async.wait_group %0;" :: "n"(n))

#define TSTRIDE 136
#define TBUF    34816

// lnproj smem
#define LNP_SA   0
#define LNP_SB0  34816
#define LNP_SB1  69632
#define LNP_XS   34816
#define LNP_WB   104448
#define LNP_SMEM 106496

// fused attn+outproj smem
#define KSTR    40
#define KVBUF   20480                 // 256 * 40 * 2 (one of K or V)
#define F_KV0   0                     // buffer 0: K | V  (40960)
#define F_KV1   40960                 // buffer 1: K | V
#define F_AV    81920                 // 256 * 136 * 2 = 69632
#define F_WO    151552                // 34816
#define F_SMEM  186368

// ---------------------------------------------------------------------------
// Kernel 0: transpose weights -> fp16
// ---------------------------------------------------------------------------
__global__ void wtransform(const float* __restrict__ Wq, const float* __restrict__ Wk,
                           const float* __restrict__ Wv, const float* __restrict__ Wg,
                           const float* __restrict__ Wo)
{
    const float* W = (blockIdx.x == 0) ? Wq : (blockIdx.x == 1) ? Wk :
                     (blockIdx.x == 2) ? Wv : (blockIdx.x == 3) ? Wg : Wo;
    __half* H = g_Wt[blockIdx.x];
    for (int e = threadIdx.x; e < CZ * CZ; e += blockDim.x) {
        int n = e >> 7, c = e & 127;
        H[e] = __float2half_rn(W[c * CZ + n]);
    }
}

// ---------------------------------------------------------------------------
// 64x32 warp-tile GEMM mainloop
// ---------------------------------------------------------------------------
__device__ __forceinline__ void gemm_warp64(float acc[16][4], u32 aBase, u32 bBase)
{
#pragma unroll
    for (int ks = 0; ks < 8; ks++) {
        u32 a0[4], a1[4], a2[4], a3[4], b0[4], b1[4];
        ldsm_x4(a0, aBase + ks * 32);
        ldsm_x4(a1, aBase + (u32)(16 * TSTRIDE) * 2 + ks * 32);
        ldsm_x4(a2, aBase + (u32)(32 * TSTRIDE) * 2 + ks * 32);
        ldsm_x4(a3, aBase + (u32)(48 * TSTRIDE) * 2 + ks * 32);
        ldsm_x4(b0, bBase + ks * 32);
        ldsm_x4(b1, bBase + (u32)(16 * TSTRIDE) * 2 + ks * 32);
        mma_f16(acc[0],  a0, b0); mma_f16(acc[1],  a0, b0 + 2);
        mma_f16(acc[2],  a0, b1); mma_f16(acc[3],  a0, b1 + 2);
        mma_f16(acc[4],  a1, b0); mma_f16(acc[5],  a1, b0 + 2);
        mma_f16(acc[6],  a1, b1); mma_f16(acc[7],  a1, b1 + 2);
        mma_f16(acc[8],  a2, b0); mma_f16(acc[9],  a2, b0 + 2);
        mma_f16(acc[10], a2, b1); mma_f16(acc[11], a2, b1 + 2);
        mma_f16(acc[12], a3, b0); mma_f16(acc[13], a3, b0 + 2);
        mma_f16(acc[14], a3, b1); mma_f16(acc[15], a3, b1 + 2);
    }
}

__device__ __forceinline__ void cp_weights(u32 sb, u32 bufOff, int m, int tid, int nthr)
{
    for (int e = tid; e < 2048; e += nthr) {
        int n = e >> 4, ch = e & 15;
        const __half* src = g_Wt[m] + n * 128 + ch * 8;
        cp16(sb + bufOff + (u32)(n * TSTRIDE + ch * 8) * 2, src);
    }
}

// ---------------------------------------------------------------------------
// Kernel 1: LN + 4 projections (1-term) + bias projection (fp16*log2e out)
// ---------------------------------------------------------------------------
__global__ __launch_bounds__(256, 2) void lnproj_mma(const float* __restrict__ x,
                                                     const float* __restrict__ gamma,
                                                     const float* __restrict__ beta,
                                                     const float* __restrict__ Wb,
                                                     const float* __restrict__ bg)
{
    extern __shared__ char sm[];
    const u32 sb = smem_u32(sm);
    const int tid = threadIdx.x, wid = tid >> 5, lane = tid & 31;
    const int wr = wid & 1, wc = wid >> 1;
    const size_t r0 = (size_t)blockIdx.x * 128;
    float* xs  = (float*)(sm + LNP_XS);
    float* sWb = (float*)(sm + LNP_WB);
    const float LOG2E = 1.4426950408889634f;

    const float4* xg = (const float4*)(x + r0 * CZ);
    for (int i = tid; i < 4096; i += 256) {
        float4 v = xg[i];
        int row = i >> 5, c = (i & 31) << 2;
        float* d = xs + row * 129 + c;
        d[0] = v.x; d[1] = v.y; d[2] = v.z; d[3] = v.w;
    }
    sWb[tid] = Wb[tid];
    sWb[tid + 256] = Wb[tid + 256];
    __syncthreads();

    // LayerNorm: 2 threads per row
    {
        int row = tid >> 1, sub = tid & 1;
        float* rp = xs + row * 129;
        float s = 0.f, s2 = 0.f;
#pragma unroll
        for (int c = sub * 64; c < sub * 64 + 64; c++) { float v = rp[c]; s += v; s2 += v * v; }
        s  += __shfl_xor_sync(0xFFFFFFFF, s, 1);
        s2 += __shfl_xor_sync(0xFFFFFFFF, s2, 1);
        float mu  = s * (1.f / 128.f);
        float var = s2 * (1.f / 128.f) - mu * mu;
        float inv = rsqrtf(var + 1e-5f);
#pragma unroll
        for (int c = sub * 64; c < sub * 64 + 64; c++)
            rp[c] = (rp[c] - mu) * inv * __ldg(gamma + c) + __ldg(beta + c);
    }
    __syncthreads();

    // bias projection (fp32 math, *log2e, fp16 store)
    for (int o = tid; o < 512; o += 256) {
        int row = o >> 2, h = o & 3;
        const float* xr = xs + row * 129;
        float s = 0.f;
#pragma unroll 8
        for (int c = 0; c < 128; c++) s += xr[c] * sWb[c * 4 + h];
        g_BiasT[(size_t)h * RTOT + r0 + row] = __float2half_rn(s * LOG2E);
    }
    for (int p = tid; p < 8192; p += 256) {
        int row = p >> 6, c = (p & 63) << 1;
        u32 hh = pack_h2(xs[row * 129 + c], xs[row * 129 + c + 1]);
        *(u32*)(sm + LNP_SA + (u32)(row * TSTRIDE + c) * 2) = hh;
    }
    __syncthreads();

    cp_weights(sb, LNP_SB0, 0, tid, 256);
    CP_COMMIT();

    const int i_ = lane >> 3, r_ = lane & 7;
    const u32 aBase = sb + LNP_SA +
        (u32)((wr * 64 + ((i_ & 1) << 3) + r_) * TSTRIDE + ((i_ >> 1) << 3)) * 2;
    const u32 bOffW = (u32)((wc * 32 + ((i_ >> 1) << 3) + r_) * TSTRIDE + ((i_ & 1) << 3)) * 2;
    const int g = lane >> 2, tig = lane & 3;

#pragma unroll
    for (int m = 0; m < 4; m++) {
        if (m < 3) { cp_weights(sb, (m & 1) ? LNP_SB0 : LNP_SB1, m + 1, tid, 256); CP_COMMIT(); }
        if (m < 3) { CP_WAIT(1); } else { CP_WAIT(0); }
        __syncthreads();

        const u32 bufOff = (m & 1) ? LNP_SB1 : LNP_SB0;
        float acc[16][4];
#pragma unroll
        for (int t = 0; t < 16; t++)
#pragma unroll
            for (int v = 0; v < 4; v++) acc[t][v] = 0.f;

        gemm_warp64(acc, aBase, sb + bufOff + bOffW);

        if (m == 0) {
            const float qs = 0.17677669529663689f * 1.4426950408889634f;
#pragma unroll
            for (int ai = 0; ai < 4; ai++) {
                size_t rowA = r0 + wr * 64 + ai * 16 + g;
                size_t rowB = rowA + 8;
#pragma unroll
                for (int ni = 0; ni < 4; ni++) {
                    int col = wc * 32 + ni * 8 + tig * 2;
                    float* a = acc[ai * 4 + ni];
                    *(u32*)(g_Qh + rowA * CZ + col) = pack_h2(a[0] * qs, a[1] * qs);
                    *(u32*)(g_Qh + rowB * CZ + col) = pack_h2(a[2] * qs, a[3] * qs);
                }
            }
        } else if (m < 3) {
            __half* O = (m == 1) ? g_Kh : g_Vh;
#pragma unroll
            for (int ai = 0; ai < 4; ai++) {
                size_t rowA = r0 + wr * 64 + ai * 16 + g;
                size_t rowB = rowA + 8;
#pragma unroll
                for (int ni = 0; ni < 4; ni++) {
                    int col = wc * 32 + ni * 8 + tig * 2;
                    float* a = acc[ai * 4 + ni];
                    *(u32*)(O + rowA * CZ + col) = pack_h2(a[0], a[1]);
                    *(u32*)(O + rowB * CZ + col) = pack_h2(a[2], a[3]);
                }
            }
        } else {
#pragma unroll
            for (int ai = 0; ai < 4; ai++) {
                size_t rowA = r0 + wr * 64 + ai * 16 + g;
                size_t rowB = rowA + 8;
#pragma unroll
                for (int ni = 0; ni < 4; ni++) {
                    int col = wc * 32 + ni * 8 + tig * 2;
                    float2 bgv = __ldg((const float2*)(bg + col));
                    float* a = acc[ai * 4 + ni];
                    float gA0 = 1.f / (1.f + __expf(-(a[0] + bgv.x)));
                    float gA1 = 1.f / (1.f + __expf(-(a[1] + bgv.y)));
                    float gB0 = 1.f / (1.f + __expf(-(a[2] + bgv.x)));
                    float gB1 = 1.f / (1.f + __expf(-(a[3] + bgv.y)));
                    *(u32*)(g_Gh + rowA * CZ + col) = pack_h2(gA0, gA1);
                    *(u32*)(g_Gh + rowB * CZ + col) = pack_h2(gB0, gB1);
                }
            }
        }
        __syncthreads();
    }
}

// ---------------------------------------------------------------------------
// Kernel 2 (fused): attention over 4 heads (K/V double-buffered, AV in smem)
// + output projection from smem. Grid 256 (one CTA per i). 8 warps x 32 j.
// ---------------------------------------------------------------------------
__device__ __forceinline__ void stage_kv(u32 sb, u32 bufOff, size_t base_i, int h, int tid)
{
    for (int e = tid; e < 2048; e += 256) {
        int buf = e >> 10, rem = e & 1023, k = rem >> 2, ch = rem & 3;
        const __half* src = ((buf == 0) ? g_Kh : g_Vh)
            + base_i + (size_t)k * CZ + h * HD + ch * 8;
        cp16(sb + bufOff + (u32)buf * KVBUF + (u32)(k * KSTR + ch * 8) * 2, src);
    }
}

__global__ __launch_bounds__(256, 1) void attn_out_fused(const float* __restrict__ bo_,
                                                         float* __restrict__ out)
{
    extern __shared__ char sm[];
    const u32 sb = smem_u32(sm);
    const int tid = threadIdx.x, wid = tid >> 5, lane = tid & 31;
    const int bi = blockIdx.x;
    const size_t base_i = (size_t)bi * NSEQ * CZ;

    // group 1: Wo + KV(head 0)
    cp_weights(sb, F_WO, 4, tid, 256);
    stage_kv(sb, F_KV0, base_i, 0, tid);
    CP_COMMIT();

    const int jr = wid * 32;
    const int r  = lane >> 2, c2 = (lane & 3) << 1;
    const int i_ = lane >> 3, r_ = lane & 7;
    const int brow = ((i_ >> 1) << 3) + r_;
    const int bcol = (i_ & 1) << 3;
    const int vsel = lane >> 3, vrow = lane & 7;
    const u32 vOff = (u32)(((vsel & 1) * 8 + vrow) * KSTR + ((vsel >> 1) << 3)) * 2;

    for (int h = 0; h < NH; h++) {
        const u32 kvOff = (h & 1) ? F_KV1 : F_KV0;
        // prefetch next head into the other buffer (safe: previous use synced)
        if (h < 3) { stage_kv(sb, (h & 1) ? F_KV0 : F_KV1, base_i, h + 1, tid); CP_COMMIT(); }
        if (h < 3) { CP_WAIT(1); } else { CP_WAIT(0); }
        __syncthreads();

        // Q fragments for this head
        u32 qh[2][2][4];
#pragma unroll
        for (int a = 0; a < 2; a++)
#pragma unroll
            for (int ks = 0; ks < 2; ks++)
#pragma unroll
                for (int reg = 0; reg < 4; reg++) {
                    int row = jr + a * 16 + r + (reg & 1) * 8;
                    int col = ks * 16 + c2 + ((reg >> 1) << 3);
                    qh[a][ks][reg] = *(const u32*)(g_Qh + base_i + (size_t)row * CZ + h * HD + col);
                }

        float oacc[2][4][4];
#pragma unroll
        for (int a = 0; a < 2; a++)
#pragma unroll
            for (int t = 0; t < 4; t++)
#pragma unroll
                for (int v = 0; v < 4; v++) oacc[a][t][v] = 0.f;
        float lsum[2][2] = {{0.f, 0.f}, {0.f, 0.f}};

        const __half* biasH = g_BiasT + (size_t)h * RTOT;

        for (int kc = 0; kc < 8; kc++) {
            float sacc[2][4][4];
#pragma unroll
            for (int a = 0; a < 2; a++)
#pragma unroll
                for (int t = 0; t < 4; t++)
#pragma unroll
                    for (int v = 0; v < 4; v++) sacc[a][t][v] = 0.f;

            // S = Q K^T over 32-k chunk
#pragma unroll
            for (int ks = 0; ks < 2; ks++) {
                u32 k0[4], k1[4];
                u32 ka = sb + kvOff + (u32)((kc * 32 + brow) * KSTR + ks * 16 + bcol) * 2;
                ldsm_x4(k0, ka);
                ldsm_x4(k1, ka + (u32)(16 * KSTR) * 2);
#pragma unroll
                for (int a = 0; a < 2; a++) {
                    mma_f16(sacc[a][0], qh[a][ks], k0);
                    mma_f16(sacc[a][1], qh[a][ks], k0 + 2);
                    mma_f16(sacc[a][2], qh[a][ks], k1);
                    mma_f16(sacc[a][3], qh[a][ks], k1 + 2);
                }
            }

            // bias + exp2 (scores pre-scaled by log2e; no-max: bounded)
#pragma unroll
            for (int a = 0; a < 2; a++) {
                const __half* b0p = biasH + (size_t)(jr + a * 16 + r) * NSEQ;
                const __half* b1p = b0p + 8 * NSEQ;
#pragma unroll
                for (int nt = 0; nt < 4; nt++) {
                    int kcol = kc * 32 + nt * 8 + c2;
                    float2 b0 = unpack_h2(__ldg((const u32*)(b0p + kcol)));
                    float2 b1 = unpack_h2(__ldg((const u32*)(b1p + kcol)));
                    float p00 = exp2f(sacc[a][nt][0] + b0.x);
                    float p01 = exp2f(sacc[a][nt][1] + b0.y);
                    float p10 = exp2f(sacc[a][nt][2] + b1.x);
                    float p11 = exp2f(sacc[a][nt][3] + b1.y);
                    sacc[a][nt][0] = p00; sacc[a][nt][1] = p01;
                    sacc[a][nt][2] = p10; sacc[a][nt][3] = p11;
                    lsum[a][0] += p00 + p01;
                    lsum[a][1] += p10 + p11;
                }
            }

            // O += P V
#pragma unroll
            for (int ks2 = 0; ks2 < 2; ks2++) {
                u32 va = sb + kvOff + KVBUF + (u32)((kc * 32 + ks2 * 16) * KSTR) * 2 + vOff;
                u32 vh[8];
                ldsm_x4_t(vh,     va);
                ldsm_x4_t(vh + 4, va + 32);
#pragma unroll
                for (int a = 0; a < 2; a++) {
                    u32 phi[4];
                    const float* s0 = sacc[a][2 * ks2];
                    const float* s1 = sacc[a][2 * ks2 + 1];
                    phi[0] = pack_h2(s0[0], s0[1]);
                    phi[1] = pack_h2(s0[2], s0[3]);
                    phi[2] = pack_h2(s1[0], s1[1]);
                    phi[3] = pack_h2(s1[2], s1[3]);
#pragma unroll
                    for (int ntd = 0; ntd < 4; ntd++)
                        mma_f16(oacc[a][ntd], phi, vh + 2 * ntd);
                }
            }
        }

#pragma unroll
        for (int a = 0; a < 2; a++)
#pragma unroll
            for (int c = 0; c < 2; c++) {
                lsum[a][c] += __shfl_xor_sync(0xFFFFFFFF, lsum[a][c], 1);
                lsum[a][c] += __shfl_xor_sync(0xFFFFFFFF, lsum[a][c], 2);
            }

        // gate + write AV into smem (cols h*32 .. h*32+31)
#pragma unroll
        for (int a = 0; a < 2; a++) {
            const float inv0 = __fdividef(1.f, lsum[a][0]);
            const float inv1 = __fdividef(1.f, lsum[a][1]);
            int row0 = jr + a * 16 + r;
            const size_t grow0 = base_i + (size_t)row0 * CZ + h * HD;
            const size_t grow1 = grow0 + 8 * CZ;
#pragma unroll
            for (int ntd = 0; ntd < 4; ntd++) {
                int col = ntd * 8 + c2;
                float2 g0 = unpack_h2(__ldg((const u32*)(g_Gh + grow0 + col)));
                float2 g1 = unpack_h2(__ldg((const u32*)(g_Gh + grow1 + col)));
                u32 o0 = pack_h2(oacc[a][ntd][0] * inv0 * g0.x,
                                 oacc[a][ntd][1] * inv0 * g0.y);
                u32 o1 = pack_h2(oacc[a][ntd][2] * inv1 * g1.x,
                                 oacc[a][ntd][3] * inv1 * g1.y);
                *(u32*)(sm + F_AV + (u32)(row0 * TSTRIDE + h * HD + col) * 2)       = o0;
                *(u32*)(sm + F_AV + (u32)((row0 + 8) * TSTRIDE + h * HD + col) * 2) = o1;
            }
        }
        __syncthreads();   // AV writes visible; KV buffer free for prefetch reuse
    }

    // ---- output projection from smem AV (256 rows x 128) ----
    const int wr = wid & 1, wc = wid >> 1;
    const u32 bBase = sb + F_WO +
        (u32)((wc * 32 + ((i_ >> 1) << 3) + r_) * TSTRIDE + ((i_ & 1) << 3)) * 2;
    const int g = lane >> 2, tig = lane & 3;

#pragma unroll
    for (int half = 0; half < 2; half++) {
        const u32 aBase = sb + F_AV +
            (u32)((half * 128 + wr * 64 + ((i_ & 1) << 3) + r_) * TSTRIDE + ((i_ >> 1) << 3)) * 2;
        float acc[16][4];
#pragma unroll
        for (int t = 0; t < 16; t++)
#pragma unroll
            for (int v = 0; v < 4; v++) acc[t][v] = 0.f;

        gemm_warp64(acc, aBase, bBase);

#pragma unroll
        for (int ai = 0; ai < 4; ai++) {
            size_t rowA = (size_t)bi * NSEQ + half * 128 + wr * 64 + ai * 16 + g;
            size_t rowB = rowA + 8;
#pragma unroll
            for (int ni = 0; ni < 4; ni++) {
                int col = wc * 32 + ni * 8 + tig * 2;
                float2 bov = __ldg((const float2*)(bo_ + col));
                float* a = acc[ai * 4 + ni];
                *(float2*)(out + rowA * CZ + col) = make_float2(a[0] + bov.x, a[1] + bov.y);
                *(float2*)(out + rowB * CZ + col) = make_float2(a[2] + bov.x, a[3] + bov.y);
            }
        }
    }
}

// ---------------------------------------------------------------------------
extern "C" void kernel_launch(void* const* d_in, const int* in_sizes, int n_in,
                              void* d_out, int out_size)
{
    const float* x     = (const float*)d_in[0];
    const float* gamma = (const float*)d_in[1];
    const float* beta  = (const float*)d_in[2];
    const float* Wq    = (const float*)d_in[3];
    const float* Wk    = (const float*)d_in[4];
    const float* Wv    = (const float*)d_in[5];
    const float* Wb    = (const float*)d_in[6];
    const float* Wg    = (const float*)d_in[7];
    const float* bg    = (const float*)d_in[8];
    const float* Wo    = (const float*)d_in[9];
    const float* bo    = (const float*)d_in[10];
    float* out = (float*)d_out;

    cudaFuncSetAttribute(lnproj_mma,     cudaFuncAttributeMaxDynamicSharedMemorySize, LNP_SMEM);
    cudaFuncSetAttribute(attn_out_fused, cudaFuncAttributeMaxDynamicSharedMemorySize, F_SMEM);

    wtransform<<<5, 256>>>(Wq, Wk, Wv, Wg, Wo);
    lnproj_mma<<<RTOT / 128, 256, LNP_SMEM>>>(x, gamma, beta, Wb, bg);
    attn_out_fused<<<NSEQ, 256, F_SMEM>>>(bo, out);
}

// round 14
// speedup vs baseline: 1.0428x; 1.0409x over previous
#include <cuda_runtime.h>
#include <cuda_fp16.h>
#include <math.h>

#define NSEQ 256
#define CZ   128
#define NH   4
#define HD   32
#define RTOT (NSEQ * NSEQ)

typedef unsigned int u32;
typedef unsigned long long u64;

// ---------------- global scratch ----------------
__device__ __half g_Qh[(size_t)RTOT * CZ];    // pre-scaled by log2e/sqrt(32)
__device__ __half g_Kh[(size_t)RTOT * CZ];
__device__ __half g_Vh[(size_t)RTOT * CZ];
__device__ __half g_Gh[(size_t)RTOT * CZ];    // gate, fp16
__device__ __half g_BiasT[(size_t)NH * RTOT]; // fp16, pre-scaled by log2e
__device__ __half g_Wt[5][CZ * CZ];

// ---------------- helpers ----------------
__device__ __forceinline__ u32 smem_u32(const void* p) {
    u32 a;
    asm("{ .reg .u64 t; cvta.to.shared.u64 t, %1; cvt.u32.u64 %0, t; }" : "=r"(a) : "l"(p));
    return a;
}
__device__ __forceinline__ void ldsm_x4(u32* r, u32 addr) {
    asm volatile("ldmatrix.sync.aligned.m8n8.x4.shared.b16 {%0,%1,%2,%3}, [%4];"
        : "=r"(r[0]), "=r"(r[1]), "=r"(r[2]), "=r"(r[3]) : "r"(addr));
}
__device__ __forceinline__ void ldsm_x4_t(u32* r, u32 addr) {
    asm volatile("ldmatrix.sync.aligned.m8n8.x4.trans.shared.b16 {%0,%1,%2,%3}, [%4];"
        : "=r"(r[0]), "=r"(r[1]), "=r"(r[2]), "=r"(r[3]) : "r"(addr));
}
__device__ __forceinline__ void mma_f16(float* d, const u32* a, const u32* b) {
    asm volatile("mma.sync.aligned.m16n8k16.row.col.f32.f16.f16.f32 "
        "{%0,%1,%2,%3}, {%4,%5,%6,%7}, {%8,%9}, {%0,%1,%2,%3};"
        : "+f"(d[0]), "+f"(d[1]), "+f"(d[2]), "+f"(d[3])
        : "r"(a[0]), "r"(a[1]), "r"(a[2]), "r"(a[3]), "r"(b[0]), "r"(b[1]));
}
__device__ __forceinline__ u32 pack_h2(float x, float y) {
    __half2 t;
    t.x = __float2half_rn(x);
    t.y = __float2half_rn(y);
    return *(u32*)&t;
}
__device__ __forceinline__ float2 unpack_h2(u32 v) {
    __half2 t = *(__half2*)&v;
    return __half22float2(t);
}
__device__ __forceinline__ void cp16(u32 dst, const void* src) {
    u64 g;
    asm("cvta.to.global.u64 %0, %1;" : "=l"(g) : "l"(src));
    asm volatile("cp.async.ca.shared.global [%0], [%1], 16;" :: "r"(dst), "l"(g));
}
#define CP_COMMIT() asm volatile("cp.async.commit_group;")
#define CP_WAIT(n)  asm volatile("cp.async.wait_group %0;" :: "n"(n))

#define TSTRIDE 136
#define TBUF    34816

// lnproj smem
#define LNP_SA   0
#define LNP_SB0  34816
#define LNP_SB1  69632
#define LNP_XS   34816
#define LNP_WB   104448
#define LNP_SMEM 106496

// fused attn+outproj smem
#define KSTR    40
#define KVBUF   20480
#define F_KV0   0
#define F_KV1   40960
#define F_AV    81920
#define F_WO    151552
#define F_SMEM  186368

// ---------------------------------------------------------------------------
// Kernel 0: transpose weights -> fp16.
// Grid (5, 8): blockIdx.x = matrix, blockIdx.y = slice of input rows.
// Coalesced float4 reads of W; scattered fp16 stores (issue-cost only).
// ---------------------------------------------------------------------------
__global__ void wtransform(const float* __restrict__ Wq, const float* __restrict__ Wk,
                           const float* __restrict__ Wv, const float* __restrict__ Wg,
                           const float* __restrict__ Wo)
{
    const float* W = (blockIdx.x == 0) ? Wq : (blockIdx.x == 1) ? Wk :
                     (blockIdx.x == 2) ? Wv : (blockIdx.x == 3) ? Wg : Wo;
    __half* H = g_Wt[blockIdx.x];
    // slice: 2048 input elements = 512 float4 per block; 256 threads x 2
    int e4 = blockIdx.y * 512 + threadIdx.x;
#pragma unroll
    for (int t = 0; t < 2; t++, e4 += 256) {
        float4 v = ((const float4*)W)[e4];
        int e = e4 * 4;                 // input index = c*128 + n
        int c = e >> 7, n = e & 127;
        H[(n + 0) * 128 + c] = __float2half_rn(v.x);
        H[(n + 1) * 128 + c] = __float2half_rn(v.y);
        H[(n + 2) * 128 + c] = __float2half_rn(v.z);
        H[(n + 3) * 128 + c] = __float2half_rn(v.w);
    }
}

// ---------------------------------------------------------------------------
// 64x32 warp-tile GEMM mainloop
// ---------------------------------------------------------------------------
__device__ __forceinline__ void gemm_warp64(float acc[16][4], u32 aBase, u32 bBase)
{
#pragma unroll
    for (int ks = 0; ks < 8; ks++) {
        u32 a0[4], a1[4], a2[4], a3[4], b0[4], b1[4];
        ldsm_x4(a0, aBase + ks * 32);
        ldsm_x4(a1, aBase + (u32)(16 * TSTRIDE) * 2 + ks * 32);
        ldsm_x4(a2, aBase + (u32)(32 * TSTRIDE) * 2 + ks * 32);
        ldsm_x4(a3, aBase + (u32)(48 * TSTRIDE) * 2 + ks * 32);
        ldsm_x4(b0, bBase + ks * 32);
        ldsm_x4(b1, bBase + (u32)(16 * TSTRIDE) * 2 + ks * 32);
        mma_f16(acc[0],  a0, b0); mma_f16(acc[1],  a0, b0 + 2);
        mma_f16(acc[2],  a0, b1); mma_f16(acc[3],  a0, b1 + 2);
        mma_f16(acc[4],  a1, b0); mma_f16(acc[5],  a1, b0 + 2);
        mma_f16(acc[6],  a1, b1); mma_f16(acc[7],  a1, b1 + 2);
        mma_f16(acc[8],  a2, b0); mma_f16(acc[9],  a2, b0 + 2);
        mma_f16(acc[10], a2, b1); mma_f16(acc[11], a2, b1 + 2);
        mma_f16(acc[12], a3, b0); mma_f16(acc[13], a3, b0 + 2);
        mma_f16(acc[14], a3, b1); mma_f16(acc[15], a3, b1 + 2);
    }
}

__device__ __forceinline__ void cp_weights(u32 sb, u32 bufOff, int m, int tid, int nthr)
{
    for (int e = tid; e < 2048; e += nthr) {
        int n = e >> 4, ch = e & 15;
        const __half* src = g_Wt[m] + n * 128 + ch * 8;
        cp16(sb + bufOff + (u32)(n * TSTRIDE + ch * 8) * 2, src);
    }
}

// ---------------------------------------------------------------------------
// Kernel 1: LN + 4 projections (1-term) + bias projection (fp16*log2e out)
// ---------------------------------------------------------------------------
__global__ __launch_bounds__(256, 2) void lnproj_mma(const float* __restrict__ x,
                                                     const float* __restrict__ gamma,
                                                     const float* __restrict__ beta,
                                                     const float* __restrict__ Wb,
                                                     const float* __restrict__ bg)
{
    extern __shared__ char sm[];
    const u32 sb = smem_u32(sm);
    const int tid = threadIdx.x, wid = tid >> 5, lane = tid & 31;
    const int wr = wid & 1, wc = wid >> 1;
    const size_t r0 = (size_t)blockIdx.x * 128;
    float* xs  = (float*)(sm + LNP_XS);
    float* sWb = (float*)(sm + LNP_WB);
    const float LOG2E = 1.4426950408889634f;

    const float4* xg = (const float4*)(x + r0 * CZ);
    for (int i = tid; i < 4096; i += 256) {
        float4 v = xg[i];
        int row = i >> 5, c = (i & 31) << 2;
        float* d = xs + row * 129 + c;
        d[0] = v.x; d[1] = v.y; d[2] = v.z; d[3] = v.w;
    }
    sWb[tid] = Wb[tid];
    sWb[tid + 256] = Wb[tid + 256];
    __syncthreads();

    // LayerNorm: 2 threads per row
    {
        int row = tid >> 1, sub = tid & 1;
        float* rp = xs + row * 129;
        float s = 0.f, s2 = 0.f;
#pragma unroll
        for (int c = sub * 64; c < sub * 64 + 64; c++) { float v = rp[c]; s += v; s2 += v * v; }
        s  += __shfl_xor_sync(0xFFFFFFFF, s, 1);
        s2 += __shfl_xor_sync(0xFFFFFFFF, s2, 1);
        float mu  = s * (1.f / 128.f);
        float var = s2 * (1.f / 128.f) - mu * mu;
        float inv = rsqrtf(var + 1e-5f);
#pragma unroll
        for (int c = sub * 64; c < sub * 64 + 64; c++)
            rp[c] = (rp[c] - mu) * inv * __ldg(gamma + c) + __ldg(beta + c);
    }
    __syncthreads();

    // bias projection (fp32 math, *log2e, fp16 store)
    for (int o = tid; o < 512; o += 256) {
        int row = o >> 2, h = o & 3;
        const float* xr = xs + row * 129;
        float s = 0.f;
#pragma unroll 8
        for (int c = 0; c < 128; c++) s += xr[c] * sWb[c * 4 + h];
        g_BiasT[(size_t)h * RTOT + r0 + row] = __float2half_rn(s * LOG2E);
    }
    for (int p = tid; p < 8192; p += 256) {
        int row = p >> 6, c = (p & 63) << 1;
        u32 hh = pack_h2(xs[row * 129 + c], xs[row * 129 + c + 1]);
        *(u32*)(sm + LNP_SA + (u32)(row * TSTRIDE + c) * 2) = hh;
    }
    __syncthreads();

    cp_weights(sb, LNP_SB0, 0, tid, 256);
    CP_COMMIT();

    const int i_ = lane >> 3, r_ = lane & 7;
    const u32 aBase = sb + LNP_SA +
        (u32)((wr * 64 + ((i_ & 1) << 3) + r_) * TSTRIDE + ((i_ >> 1) << 3)) * 2;
    const u32 bOffW = (u32)((wc * 32 + ((i_ >> 1) << 3) + r_) * TSTRIDE + ((i_ & 1) << 3)) * 2;
    const int g = lane >> 2, tig = lane & 3;

#pragma unroll
    for (int m = 0; m < 4; m++) {
        if (m < 3) { cp_weights(sb, (m & 1) ? LNP_SB0 : LNP_SB1, m + 1, tid, 256); CP_COMMIT(); }
        if (m < 3) { CP_WAIT(1); } else { CP_WAIT(0); }
        __syncthreads();

        const u32 bufOff = (m & 1) ? LNP_SB1 : LNP_SB0;
        float acc[16][4];
#pragma unroll
        for (int t = 0; t < 16; t++)
#pragma unroll
            for (int v = 0; v < 4; v++) acc[t][v] = 0.f;

        gemm_warp64(acc, aBase, sb + bufOff + bOffW);

        if (m == 0) {
            const float qs = 0.17677669529663689f * 1.4426950408889634f;
#pragma unroll
            for (int ai = 0; ai < 4; ai++) {
                size_t rowA = r0 + wr * 64 + ai * 16 + g;
                size_t rowB = rowA + 8;
#pragma unroll
                for (int ni = 0; ni < 4; ni++) {
                    int col = wc * 32 + ni * 8 + tig * 2;
                    float* a = acc[ai * 4 + ni];
                    *(u32*)(g_Qh + rowA * CZ + col) = pack_h2(a[0] * qs, a[1] * qs);
                    *(u32*)(g_Qh + rowB * CZ + col) = pack_h2(a[2] * qs, a[3] * qs);
                }
            }
        } else if (m < 3) {
            __half* O = (m == 1) ? g_Kh : g_Vh;
#pragma unroll
            for (int ai = 0; ai < 4; ai++) {
                size_t rowA = r0 + wr * 64 + ai * 16 + g;
                size_t rowB = rowA + 8;
#pragma unroll
                for (int ni = 0; ni < 4; ni++) {
                    int col = wc * 32 + ni * 8 + tig * 2;
                    float* a = acc[ai * 4 + ni];
                    *(u32*)(O + rowA * CZ + col) = pack_h2(a[0], a[1]);
                    *(u32*)(O + rowB * CZ + col) = pack_h2(a[2], a[3]);
                }
            }
        } else {
#pragma unroll
            for (int ai = 0; ai < 4; ai++) {
                size_t rowA = r0 + wr * 64 + ai * 16 + g;
                size_t rowB = rowA + 8;
#pragma unroll
                for (int ni = 0; ni < 4; ni++) {
                    int col = wc * 32 + ni * 8 + tig * 2;
                    float2 bgv = __ldg((const float2*)(bg + col));
                    float* a = acc[ai * 4 + ni];
                    float gA0 = 1.f / (1.f + __expf(-(a[0] + bgv.x)));
                    float gA1 = 1.f / (1.f + __expf(-(a[1] + bgv.y)));
                    float gB0 = 1.f / (1.f + __expf(-(a[2] + bgv.x)));
                    float gB1 = 1.f / (1.f + __expf(-(a[3] + bgv.y)));
                    *(u32*)(g_Gh + rowA * CZ + col) = pack_h2(gA0, gA1);
                    *(u32*)(g_Gh + rowB * CZ + col) = pack_h2(gB0, gB1);
                }
            }
        }
        __syncthreads();
    }
}

// ---------------------------------------------------------------------------
// Kernel 2 (fused): attention over 4 heads + output projection from smem.
// Grid 256 (one CTA per i). 8 warps x 32 j.
// ---------------------------------------------------------------------------
__device__ __forceinline__ void stage_kv(u32 sb, u32 bufOff, size_t base_i, int h, int tid)
{
    for (int e = tid; e < 2048; e += 256) {
        int buf = e >> 10, rem = e & 1023, k = rem >> 2, ch = rem & 3;
        const __half* src = ((buf == 0) ? g_Kh : g_Vh)
            + base_i + (size_t)k * CZ + h * HD + ch * 8;
        cp16(sb + bufOff + (u32)buf * KVBUF + (u32)(k * KSTR + ch * 8) * 2, src);
    }
}

__global__ __launch_bounds__(256, 1) void attn_out_fused(const float* __restrict__ bo_,
                                                         float* __restrict__ out)
{
    extern __shared__ char sm[];
    const u32 sb = smem_u32(sm);
    const int tid = threadIdx.x, wid = tid >> 5, lane = tid & 31;
    const int bi = blockIdx.x;
    const size_t base_i = (size_t)bi * NSEQ * CZ;

    cp_weights(sb, F_WO, 4, tid, 256);
    stage_kv(sb, F_KV0, base_i, 0, tid);
    CP_COMMIT();

    const int jr = wid * 32;
    const int r  = lane >> 2, c2 = (lane & 3) << 1;
    const int i_ = lane >> 3, r_ = lane & 7;
    const int brow = ((i_ >> 1) << 3) + r_;
    const int bcol = (i_ & 1) << 3;
    const int vsel = lane >> 3, vrow = lane & 7;
    const u32 vOff = (u32)(((vsel & 1) * 8 + vrow) * KSTR + ((vsel >> 1) << 3)) * 2;

    for (int h = 0; h < NH; h++) {
        const u32 kvOff = (h & 1) ? F_KV1 : F_KV0;
        if (h < 3) { stage_kv(sb, (h & 1) ? F_KV0 : F_KV1, base_i, h + 1, tid); CP_COMMIT(); }
        if (h < 3) { CP_WAIT(1); } else { CP_WAIT(0); }
        __syncthreads();

        u32 qh[2][2][4];
#pragma unroll
        for (int a = 0; a < 2; a++)
#pragma unroll
            for (int ks = 0; ks < 2; ks++)
#pragma unroll
                for (int reg = 0; reg < 4; reg++) {
                    int row = jr + a * 16 + r + (reg & 1) * 8;
                    int col = ks * 16 + c2 + ((reg >> 1) << 3);
                    qh[a][ks][reg] = *(const u32*)(g_Qh + base_i + (size_t)row * CZ + h * HD + col);
                }

        float oacc[2][4][4];
#pragma unroll
        for (int a = 0; a < 2; a++)
#pragma unroll
            for (int t = 0; t < 4; t++)
#pragma unroll
                for (int v = 0; v < 4; v++) oacc[a][t][v] = 0.f;
        float lsum[2][2] = {{0.f, 0.f}, {0.f, 0.f}};

        const __half* biasH = g_BiasT + (size_t)h * RTOT;

        for (int kc = 0; kc < 8; kc++) {
            float sacc[2][4][4];
#pragma unroll
            for (int a = 0; a < 2; a++)
#pragma unroll
                for (int t = 0; t < 4; t++)
#pragma unroll
                    for (int v = 0; v < 4; v++) sacc[a][t][v] = 0.f;

#pragma unroll
            for (int ks = 0; ks < 2; ks++) {
                u32 k0[4], k1[4];
                u32 ka = sb + kvOff + (u32)((kc * 32 + brow) * KSTR + ks * 16 + bcol) * 2;
                ldsm_x4(k0, ka);
                ldsm_x4(k1, ka + (u32)(16 * KSTR) * 2);
#pragma unroll
                for (int a = 0; a < 2; a++) {
                    mma_f16(sacc[a][0], qh[a][ks], k0);
                    mma_f16(sacc[a][1], qh[a][ks], k0 + 2);
                    mma_f16(sacc[a][2], qh[a][ks], k1);
                    mma_f16(sacc[a][3], qh[a][ks], k1 + 2);
                }
            }

#pragma unroll
            for (int a = 0; a < 2; a++) {
                const __half* b0p = biasH + (size_t)(jr + a * 16 + r) * NSEQ;
                const __half* b1p = b0p + 8 * NSEQ;
#pragma unroll
                for (int nt = 0; nt < 4; nt++) {
                    int kcol = kc * 32 + nt * 8 + c2;
                    float2 b0 = unpack_h2(__ldg((const u32*)(b0p + kcol)));
                    float2 b1 = unpack_h2(__ldg((const u32*)(b1p + kcol)));
                    float p00 = exp2f(sacc[a][nt][0] + b0.x);
                    float p01 = exp2f(sacc[a][nt][1] + b0.y);
                    float p10 = exp2f(sacc[a][nt][2] + b1.x);
                    float p11 = exp2f(sacc[a][nt][3] + b1.y);
                    sacc[a][nt][0] = p00; sacc[a][nt][1] = p01;
                    sacc[a][nt][2] = p10; sacc[a][nt][3] = p11;
                    lsum[a][0] += p00 + p01;
                    lsum[a][1] += p10 + p11;
                }
            }

#pragma unroll
            for (int ks2 = 0; ks2 < 2; ks2++) {
                u32 va = sb + kvOff + KVBUF + (u32)((kc * 32 + ks2 * 16) * KSTR) * 2 + vOff;
                u32 vh[8];
                ldsm_x4_t(vh,     va);
                ldsm_x4_t(vh + 4, va + 32);
#pragma unroll
                for (int a = 0; a < 2; a++) {
                    u32 phi[4];
                    const float* s0 = sacc[a][2 * ks2];
                    const float* s1 = sacc[a][2 * ks2 + 1];
                    phi[0] = pack_h2(s0[0], s0[1]);
                    phi[1] = pack_h2(s0[2], s0[3]);
                    phi[2] = pack_h2(s1[0], s1[1]);
                    phi[3] = pack_h2(s1[2], s1[3]);
#pragma unroll
                    for (int ntd = 0; ntd < 4; ntd++)
                        mma_f16(oacc[a][ntd], phi, vh + 2 * ntd);
                }
            }
        }

#pragma unroll
        for (int a = 0; a < 2; a++)
#pragma unroll
            for (int c = 0; c < 2; c++) {
                lsum[a][c] += __shfl_xor_sync(0xFFFFFFFF, lsum[a][c], 1);
                lsum[a][c] += __shfl_xor_sync(0xFFFFFFFF, lsum[a][c], 2);
            }

#pragma unroll
        for (int a = 0; a < 2; a++) {
            const float inv0 = __fdividef(1.f, lsum[a][0]);
            const float inv1 = __fdividef(1.f, lsum[a][1]);
            int row0 = jr + a * 16 + r;
            const size_t grow0 = base_i + (size_t)row0 * CZ + h * HD;
            const size_t grow1 = grow0 + 8 * CZ;
#pragma unroll
            for (int ntd = 0; ntd < 4; ntd++) {
                int col = ntd * 8 + c2;
                float2 g0 = unpack_h2(__ldg((const u32*)(g_Gh + grow0 + col)));
                float2 g1 = unpack_h2(__ldg((const u32*)(g_Gh + grow1 + col)));
                u32 o0 = pack_h2(oacc[a][ntd][0] * inv0 * g0.x,
                                 oacc[a][ntd][1] * inv0 * g0.y);
                u32 o1 = pack_h2(oacc[a][ntd][2] * inv1 * g1.x,
                                 oacc[a][ntd][3] * inv1 * g1.y);
                *(u32*)(sm + F_AV + (u32)(row0 * TSTRIDE + h * HD + col) * 2)       = o0;
                *(u32*)(sm + F_AV + (u32)((row0 + 8) * TSTRIDE + h * HD + col) * 2) = o1;
            }
        }
        __syncthreads();
    }

    // ---- output projection from smem AV (256 rows x 128) ----
    const int wr = wid & 1, wc = wid >> 1;
    const u32 bBase = sb + F_WO +
        (u32)((wc * 32 + ((i_ >> 1) << 3) + r_) * TSTRIDE + ((i_ & 1) << 3)) * 2;
    const int g = lane >> 2, tig = lane & 3;

#pragma unroll
    for (int half = 0; half < 2; half++) {
        const u32 aBase = sb + F_AV +
            (u32)((half * 128 + wr * 64 + ((i_ & 1) << 3) + r_) * TSTRIDE + ((i_ >> 1) << 3)) * 2;
        float acc[16][4];
#pragma unroll
        for (int t = 0; t < 16; t++)
#pragma unroll
            for (int v = 0; v < 4; v++) acc[t][v] = 0.f;

        gemm_warp64(acc, aBase, bBase);

#pragma unroll
        for (int ai = 0; ai < 4; ai++) {
            size_t rowA = (size_t)bi * NSEQ + half * 128 + wr * 64 + ai * 16 + g;
            size_t rowB = rowA + 8;
#pragma unroll
            for (int ni = 0; ni < 4; ni++) {
                int col = wc * 32 + ni * 8 + tig * 2;
                float2 bov = __ldg((const float2*)(bo_ + col));
                float* a = acc[ai * 4 + ni];
                *(float2*)(out + rowA * CZ + col) = make_float2(a[0] + bov.x, a[1] + bov.y);
                *(float2*)(out + rowB * CZ + col) = make_float2(a[2] + bov.x, a[3] + bov.y);
            }
        }
    }
}

// ---------------------------------------------------------------------------
extern "C" void kernel_launch(void* const* d_in, const int* in_sizes, int n_in,
                              void* d_out, int out_size)
{
    const float* x     = (const float*)d_in[0];
    const float* gamma = (const float*)d_in[1];
    const float* beta  = (const float*)d_in[2];
    const float* Wq    = (const float*)d_in[3];
    const float* Wk    = (const float*)d_in[4];
    const float* Wv    = (const float*)d_in[5];
    const float* Wb    = (const float*)d_in[6];
    const float* Wg    = (const float*)d_in[7];
    const float* bg    = (const float*)d_in[8];
    const float* Wo    = (const float*)d_in[9];
    const float* bo    = (const float*)d_in[10];
    float* out = (float*)d_out;

    cudaFuncSetAttribute(lnproj_mma,     cudaFuncAttributeMaxDynamicSharedMemorySize, LNP_SMEM);
    cudaFuncSetAttribute(attn_out_fused, cudaFuncAttributeMaxDynamicSharedMemorySize, F_SMEM);

    dim3 gw(5, 8);
    wtransform<<<gw, 256>>>(Wq, Wk, Wv, Wg, Wo);
    lnproj_mma<<<RTOT / 128, 256, LNP_SMEM>>>(x, gamma, beta, Wb, bg);
    attn_out_fused<<<NSEQ, 256, F_SMEM>>>(bo, out);
}

// round 15
// speedup vs baseline: 1.1043x; 1.0589x over previous
#include <cuda_runtime.h>
#include <cuda_fp16.h>
#include <math.h>

#define NSEQ 256
#define CZ   128
#define NH   4
#define HD   32
#define RTOT (NSEQ * NSEQ)

typedef unsigned int u32;
typedef unsigned long long u64;

// ---------------- global scratch ----------------
__device__ __half g_Qh[(size_t)RTOT * CZ];    // pre-scaled by log2e/sqrt(32)
__device__ __half g_Kh[(size_t)RTOT * CZ];
__device__ __half g_Vh[(size_t)RTOT * CZ];
__device__ __half g_Gh[(size_t)RTOT * CZ];    // gate, fp16
__device__ __half g_BiasT[(size_t)NH * RTOT]; // fp16, pre-scaled by log2e
__device__ __half g_Wt[5][CZ * CZ];

// ---------------- helpers ----------------
__device__ __forceinline__ u32 smem_u32(const void* p) {
    u32 a;
    asm("{ .reg .u64 t; cvta.to.shared.u64 t, %1; cvt.u32.u64 %0, t; }" : "=r"(a) : "l"(p));
    return a;
}
__device__ __forceinline__ void ldsm_x4(u32* r, u32 addr) {
    asm volatile("ldmatrix.sync.aligned.m8n8.x4.shared.b16 {%0,%1,%2,%3}, [%4];"
        : "=r"(r[0]), "=r"(r[1]), "=r"(r[2]), "=r"(r[3]) : "r"(addr));
}
__device__ __forceinline__ void ldsm_x4_t(u32* r, u32 addr) {
    asm volatile("ldmatrix.sync.aligned.m8n8.x4.trans.shared.b16 {%0,%1,%2,%3}, [%4];"
        : "=r"(r[0]), "=r"(r[1]), "=r"(r[2]), "=r"(r[3]) : "r"(addr));
}
__device__ __forceinline__ void mma_f16(float* d, const u32* a, const u32* b) {
    asm volatile("mma.sync.aligned.m16n8k16.row.col.f32.f16.f16.f32 "
        "{%0,%1,%2,%3}, {%4,%5,%6,%7}, {%8,%9}, {%0,%1,%2,%3};"
        : "+f"(d[0]), "+f"(d[1]), "+f"(d[2]), "+f"(d[3])
        : "r"(a[0]), "r"(a[1]), "r"(a[2]), "r"(a[3]), "r"(b[0]), "r"(b[1]));
}
__device__ __forceinline__ u32 pack_h2(float x, float y) {
    __half2 t;
    t.x = __float2half_rn(x);
    t.y = __float2half_rn(y);
    return *(u32*)&t;
}
__device__ __forceinline__ float2 unpack_h2(u32 v) {
    __half2 t = *(__half2*)&v;
    return __half22float2(t);
}
__device__ __forceinline__ void cp16(u32 dst, const void* src) {
    u64 g;
    asm("cvta.to.global.u64 %0, %1;" : "=l"(g) : "l"(src));
    asm volatile("cp.async.ca.shared.global [%0], [%1], 16;" :: "r"(dst), "l"(g));
}
#define CP_COMMIT() asm volatile("cp.async.commit_group;")
#define CP_WAIT(n)  asm volatile("cp.async.wait_group %0;" :: "n"(n))

#define TSTRIDE 136
#define TBUF    34816

// lnproj smem
#define LNP_SA   0
#define LNP_SB0  34816
#define LNP_SB1  69632
#define LNP_XS   34816        // fp32 x-tile overlays SB0+SB1 (66048)
#define LNP_WB   104448       // Wb half2-packed [64 kpair][8 h] = 2048 B
#define LNP_SMEM 106496

// fused attn+outproj smem
#define KSTR    40
#define KVBUF   20480
#define F_KV0   0
#define F_KV1   40960
#define F_AV    81920
#define F_WO    151552
#define F_SMEM  186368

// ---------------------------------------------------------------------------
// Kernel 0: transpose weights -> fp16. Grid (5, 16), 1 float4/thread.
// ---------------------------------------------------------------------------
__global__ void wtransform(const float* __restrict__ Wq, const float* __restrict__ Wk,
                           const float* __restrict__ Wv, const float* __restrict__ Wg,
                           const float* __restrict__ Wo)
{
    const float* W = (blockIdx.x == 0) ? Wq : (blockIdx.x == 1) ? Wk :
                     (blockIdx.x == 2) ? Wv : (blockIdx.x == 3) ? Wg : Wo;
    __half* H = g_Wt[blockIdx.x];
    int e4 = blockIdx.y * 256 + threadIdx.x;
    float4 v = ((const float4*)W)[e4];
    int e = e4 * 4;
    int c = e >> 7, n = e & 127;
    H[(n + 0) * 128 + c] = __float2half_rn(v.x);
    H[(n + 1) * 128 + c] = __float2half_rn(v.y);
    H[(n + 2) * 128 + c] = __float2half_rn(v.z);
    H[(n + 3) * 128 + c] = __float2half_rn(v.w);
}

// ---------------------------------------------------------------------------
// 64x32 warp-tile GEMM mainloop
// ---------------------------------------------------------------------------
__device__ __forceinline__ void gemm_warp64(float acc[16][4], u32 aBase, u32 bBase)
{
#pragma unroll
    for (int ks = 0; ks < 8; ks++) {
        u32 a0[4], a1[4], a2[4], a3[4], b0[4], b1[4];
        ldsm_x4(a0, aBase + ks * 32);
        ldsm_x4(a1, aBase + (u32)(16 * TSTRIDE) * 2 + ks * 32);
        ldsm_x4(a2, aBase + (u32)(32 * TSTRIDE) * 2 + ks * 32);
        ldsm_x4(a3, aBase + (u32)(48 * TSTRIDE) * 2 + ks * 32);
        ldsm_x4(b0, bBase + ks * 32);
        ldsm_x4(b1, bBase + (u32)(16 * TSTRIDE) * 2 + ks * 32);
        mma_f16(acc[0],  a0, b0); mma_f16(acc[1],  a0, b0 + 2);
        mma_f16(acc[2],  a0, b1); mma_f16(acc[3],  a0, b1 + 2);
        mma_f16(acc[4],  a1, b0); mma_f16(acc[5],  a1, b0 + 2);
        mma_f16(acc[6],  a1, b1); mma_f16(acc[7],  a1, b1 + 2);
        mma_f16(acc[8],  a2, b0); mma_f16(acc[9],  a2, b0 + 2);
        mma_f16(acc[10], a2, b1); mma_f16(acc[11], a2, b1 + 2);
        mma_f16(acc[12], a3, b0); mma_f16(acc[13], a3, b0 + 2);
        mma_f16(acc[14], a3, b1); mma_f16(acc[15], a3, b1 + 2);
    }
}

__device__ __forceinline__ void cp_weights(u32 sb, u32 bufOff, int m, int tid, int nthr)
{
    for (int e = tid; e < 2048; e += nthr) {
        int n = e >> 4, ch = e & 15;
        const __half* src = g_Wt[m] + n * 128 + ch * 8;
        cp16(sb + bufOff + (u32)(n * TSTRIDE + ch * 8) * 2, src);
    }
}

// ---------------------------------------------------------------------------
// Kernel 1: LN (fp16 direct to A-tile) + bias via MMA + 4 projections (1-term)
// ---------------------------------------------------------------------------
__global__ __launch_bounds__(256, 2) void lnproj_mma(const float* __restrict__ x,
                                                     const float* __restrict__ gamma,
                                                     const float* __restrict__ beta,
                                                     const float* __restrict__ Wb,
                                                     const float* __restrict__ bg)
{
    extern __shared__ char sm[];
    const u32 sb = smem_u32(sm);
    const int tid = threadIdx.x, wid = tid >> 5, lane = tid & 31;
    const int wr = wid & 1, wc = wid >> 1;
    const size_t r0 = (size_t)blockIdx.x * 128;
    float* xs = (float*)(sm + LNP_XS);
    __half* sWbh = (__half*)(sm + LNP_WB);
    const float LOG2E = 1.4426950408889634f;

    // load x tile + Wb (half2-packed along k, padded h 4..7 = 0)
    const float4* xg = (const float4*)(x + r0 * CZ);
    for (int i = tid; i < 4096; i += 256) {
        float4 v = xg[i];
        int row = i >> 5, c = (i & 31) << 2;
        float* d = xs + row * 129 + c;
        d[0] = v.x; d[1] = v.y; d[2] = v.z; d[3] = v.w;
    }
    for (int e = tid; e < 1024; e += 256) {
        int c = e >> 3, h = e & 7;
        float v = (h < 4) ? __ldg(Wb + c * 4 + h) : 0.f;
        sWbh[((c >> 1) * 8 + h) * 2 + (c & 1)] = __float2half_rn(v);
    }
    __syncthreads();

    // LayerNorm: 2 threads per row; write fp16 DIRECTLY into A-tile
    {
        int row = tid >> 1, sub = tid & 1;
        float* rp = xs + row * 129;
        float s = 0.f, s2 = 0.f;
#pragma unroll
        for (int c = sub * 64; c < sub * 64 + 64; c++) { float v = rp[c]; s += v; s2 += v * v; }
        s  += __shfl_xor_sync(0xFFFFFFFF, s, 1);
        s2 += __shfl_xor_sync(0xFFFFFFFF, s2, 1);
        float mu  = s * (1.f / 128.f);
        float var = s2 * (1.f / 128.f) - mu * mu;
        float inv = rsqrtf(var + 1e-5f);
#pragma unroll
        for (int c = sub * 64; c < sub * 64 + 64; c += 2) {
            float v0 = (rp[c]     - mu) * inv * __ldg(gamma + c)     + __ldg(beta + c);
            float v1 = (rp[c + 1] - mu) * inv * __ldg(gamma + c + 1) + __ldg(beta + c + 1);
            *(u32*)(sm + LNP_SA + (u32)(row * TSTRIDE + c) * 2) = pack_h2(v0, v1);
        }
    }
    __syncthreads();   // A-tile ready; xs no longer needed

    // start m=0 weight copy (overlaps bias MMA below)
    cp_weights(sb, LNP_SB0, 0, tid, 256);
    CP_COMMIT();

    const int i_ = lane >> 3, r_ = lane & 7;
    const u32 aBase = sb + LNP_SA +
        (u32)((wr * 64 + ((i_ & 1) << 3) + r_) * TSTRIDE + ((i_ >> 1) << 3)) * 2;
    const u32 bOffW = (u32)((wc * 32 + ((i_ >> 1) << 3) + r_) * TSTRIDE + ((i_ & 1) << 3)) * 2;
    const int g = lane >> 2, tig = lane & 3;

    // ---- bias projection via MMA: each warp does 16 rows x 8 cols ----
    {
        const u32 aB = sb + LNP_SA +
            (u32)((wid * 16 + ((i_ & 1) << 3) + r_) * TSTRIDE + ((i_ >> 1) << 3)) * 2;
        const u32* wb32 = (const u32*)sWbh;
        float dacc[4] = {0.f, 0.f, 0.f, 0.f};
#pragma unroll
        for (int ks = 0; ks < 8; ks++) {
            u32 a[4], b[2];
            ldsm_x4(a, aB + ks * 32);
            b[0] = wb32[(ks * 8 + tig) * 8 + g];
            b[1] = wb32[(ks * 8 + 4 + tig) * 8 + g];
            mma_f16(dacc, a, b);
        }
        int row = wid * 16 + g;
        int col0 = tig * 2;
        if (col0 < NH) {
            g_BiasT[(size_t)col0 * RTOT + r0 + row]           = __float2half_rn(dacc[0] * LOG2E);
            g_BiasT[(size_t)(col0 + 1) * RTOT + r0 + row]     = __float2half_rn(dacc[1] * LOG2E);
            g_BiasT[(size_t)col0 * RTOT + r0 + row + 8]       = __float2half_rn(dacc[2] * LOG2E);
            g_BiasT[(size_t)(col0 + 1) * RTOT + r0 + row + 8] = __float2half_rn(dacc[3] * LOG2E);
        }
    }

#pragma unroll
    for (int m = 0; m < 4; m++) {
        if (m < 3) { cp_weights(sb, (m & 1) ? LNP_SB0 : LNP_SB1, m + 1, tid, 256); CP_COMMIT(); }
        if (m < 3) { CP_WAIT(1); } else { CP_WAIT(0); }
        __syncthreads();

        const u32 bufOff = (m & 1) ? LNP_SB1 : LNP_SB0;
        float acc[16][4];
#pragma unroll
        for (int t = 0; t < 16; t++)
#pragma unroll
            for (int v = 0; v < 4; v++) acc[t][v] = 0.f;

        gemm_warp64(acc, aBase, sb + bufOff + bOffW);

        if (m == 0) {
            const float qs = 0.17677669529663689f * 1.4426950408889634f;
#pragma unroll
            for (int ai = 0; ai < 4; ai++) {
                size_t rowA = r0 + wr * 64 + ai * 16 + g;
                size_t rowB = rowA + 8;
#pragma unroll
                for (int ni = 0; ni < 4; ni++) {
                    int col = wc * 32 + ni * 8 + tig * 2;
                    float* a = acc[ai * 4 + ni];
                    *(u32*)(g_Qh + rowA * CZ + col) = pack_h2(a[0] * qs, a[1] * qs);
                    *(u32*)(g_Qh + rowB * CZ + col) = pack_h2(a[2] * qs, a[3] * qs);
                }
            }
        } else if (m < 3) {
            __half* O = (m == 1) ? g_Kh : g_Vh;
#pragma unroll
            for (int ai = 0; ai < 4; ai++) {
                size_t rowA = r0 + wr * 64 + ai * 16 + g;
                size_t rowB = rowA + 8;
#pragma unroll
                for (int ni = 0; ni < 4; ni++) {
                    int col = wc * 32 + ni * 8 + tig * 2;
                    float* a = acc[ai * 4 + ni];
                    *(u32*)(O + rowA * CZ + col) = pack_h2(a[0], a[1]);
                    *(u32*)(O + rowB * CZ + col) = pack_h2(a[2], a[3]);
                }
            }
        } else {
#pragma unroll
            for (int ai = 0; ai < 4; ai++) {
                size_t rowA = r0 + wr * 64 + ai * 16 + g;
                size_t rowB = rowA + 8;
#pragma unroll
                for (int ni = 0; ni < 4; ni++) {
                    int col = wc * 32 + ni * 8 + tig * 2;
                    float2 bgv = __ldg((const float2*)(bg + col));
                    float* a = acc[ai * 4 + ni];
                    float gA0 = 1.f / (1.f + __expf(-(a[0] + bgv.x)));
                    float gA1 = 1.f / (1.f + __expf(-(a[1] + bgv.y)));
                    float gB0 = 1.f / (1.f + __expf(-(a[2] + bgv.x)));
                    float gB1 = 1.f / (1.f + __expf(-(a[3] + bgv.y)));
                    *(u32*)(g_Gh + rowA * CZ + col) = pack_h2(gA0, gA1);
                    *(u32*)(g_Gh + rowB * CZ + col) = pack_h2(gB0, gB1);
                }
            }
        }
        __syncthreads();
    }
}

// ---------------------------------------------------------------------------
// Kernel 2 (fused): attention over 4 heads + output projection from smem.
// ---------------------------------------------------------------------------
__device__ __forceinline__ void stage_kv(u32 sb, u32 bufOff, size_t base_i, int h, int tid)
{
    for (int e = tid; e < 2048; e += 256) {
        int buf = e >> 10, rem = e & 1023, k = rem >> 2, ch = rem & 3;
        const __half* src = ((buf == 0) ? g_Kh : g_Vh)
            + base_i + (size_t)k * CZ + h * HD + ch * 8;
        cp16(sb + bufOff + (u32)buf * KVBUF + (u32)(k * KSTR + ch * 8) * 2, src);
    }
}

__global__ __launch_bounds__(256, 1) void attn_out_fused(const float* __restrict__ bo_,
                                                         float* __restrict__ out)
{
    extern __shared__ char sm[];
    const u32 sb = smem_u32(sm);
    const int tid = threadIdx.x, wid = tid >> 5, lane = tid & 31;
    const int bi = blockIdx.x;
    const size_t base_i = (size_t)bi * NSEQ * CZ;

    cp_weights(sb, F_WO, 4, tid, 256);
    stage_kv(sb, F_KV0, base_i, 0, tid);
    CP_COMMIT();

    const int jr = wid * 32;
    const int r  = lane >> 2, c2 = (lane & 3) << 1;
    const int i_ = lane >> 3, r_ = lane & 7;
    const int brow = ((i_ >> 1) << 3) + r_;
    const int bcol = (i_ & 1) << 3;
    const int vsel = lane >> 3, vrow = lane & 7;
    const u32 vOff = (u32)(((vsel & 1) * 8 + vrow) * KSTR + ((vsel >> 1) << 3)) * 2;

    for (int h = 0; h < NH; h++) {
        const u32 kvOff = (h & 1) ? F_KV1 : F_KV0;
        if (h < 3) { stage_kv(sb, (h & 1) ? F_KV0 : F_KV1, base_i, h + 1, tid); CP_COMMIT(); }
        if (h < 3) { CP_WAIT(1); } else { CP_WAIT(0); }
        __syncthreads();

        u32 qh[2][2][4];
#pragma unroll
        for (int a = 0; a < 2; a++)
#pragma unroll
            for (int ks = 0; ks < 2; ks++)
#pragma unroll
                for (int reg = 0; reg < 4; reg++) {
                    int row = jr + a * 16 + r + (reg & 1) * 8;
                    int col = ks * 16 + c2 + ((reg >> 1) << 3);
                    qh[a][ks][reg] = *(const u32*)(g_Qh + base_i + (size_t)row * CZ + h * HD + col);
                }

        float oacc[2][4][4];
#pragma unroll
        for (int a = 0; a < 2; a++)
#pragma unroll
            for (int t = 0; t < 4; t++)
#pragma unroll
                for (int v = 0; v < 4; v++) oacc[a][t][v] = 0.f;
        float lsum[2][2] = {{0.f, 0.f}, {0.f, 0.f}};

        const __half* biasH = g_BiasT + (size_t)h * RTOT;

        for (int kc = 0; kc < 8; kc++) {
            float sacc[2][4][4];
#pragma unroll
            for (int a = 0; a < 2; a++)
#pragma unroll
                for (int t = 0; t < 4; t++)
#pragma unroll
                    for (int v = 0; v < 4; v++) sacc[a][t][v] = 0.f;

#pragma unroll
            for (int ks = 0; ks < 2; ks++) {
                u32 k0[4], k1[4];
                u32 ka = sb + kvOff + (u32)((kc * 32 + brow) * KSTR + ks * 16 + bcol) * 2;
                ldsm_x4(k0, ka);
                ldsm_x4(k1, ka + (u32)(16 * KSTR) * 2);
#pragma unroll
                for (int a = 0; a < 2; a++) {
                    mma_f16(sacc[a][0], qh[a][ks], k0);
                    mma_f16(sacc[a][1], qh[a][ks], k0 + 2);
                    mma_f16(sacc[a][2], qh[a][ks], k1);
                    mma_f16(sacc[a][3], qh[a][ks], k1 + 2);
                }
            }

#pragma unroll
            for (int a = 0; a < 2; a++) {
                const __half* b0p = biasH + (size_t)(jr + a * 16 + r) * NSEQ;
                const __half* b1p = b0p + 8 * NSEQ;
#pragma unroll
                for (int nt = 0; nt < 4; nt++) {
                    int kcol = kc * 32 + nt * 8 + c2;
                    float2 b0 = unpack_h2(__ldg((const u32*)(b0p + kcol)));
                    float2 b1 = unpack_h2(__ldg((const u32*)(b1p + kcol)));
                    float p00 = exp2f(sacc[a][nt][0] + b0.x);
                    float p01 = exp2f(sacc[a][nt][1] + b0.y);
                    float p10 = exp2f(sacc[a][nt][2] + b1.x);
                    float p11 = exp2f(sacc[a][nt][3] + b1.y);
                    sacc[a][nt][0] = p00; sacc[a][nt][1] = p01;
                    sacc[a][nt][2] = p10; sacc[a][nt][3] = p11;
                    lsum[a][0] += p00 + p01;
                    lsum[a][1] += p10 + p11;
                }
            }

#pragma unroll
            for (int ks2 = 0; ks2 < 2; ks2++) {
                u32 va = sb + kvOff + KVBUF + (u32)((kc * 32 + ks2 * 16) * KSTR) * 2 + vOff;
                u32 vh[8];
                ldsm_x4_t(vh,     va);
                ldsm_x4_t(vh + 4, va + 32);
#pragma unroll
                for (int a = 0; a < 2; a++) {
                    u32 phi[4];
                    const float* s0 = sacc[a][2 * ks2];
                    const float* s1 = sacc[a][2 * ks2 + 1];
                    phi[0] = pack_h2(s0[0], s0[1]);
                    phi[1] = pack_h2(s0[2], s0[3]);
                    phi[2] = pack_h2(s1[0], s1[1]);
                    phi[3] = pack_h2(s1[2], s1[3]);
#pragma unroll
                    for (int ntd = 0; ntd < 4; ntd++)
                        mma_f16(oacc[a][ntd], phi, vh + 2 * ntd);
                }
            }
        }

#pragma unroll
        for (int a = 0; a < 2; a++)
#pragma unroll
            for (int c = 0; c < 2; c++) {
                lsum[a][c] += __shfl_xor_sync(0xFFFFFFFF, lsum[a][c], 1);
                lsum[a][c] += __shfl_xor_sync(0xFFFFFFFF, lsum[a][c], 2);
            }

#pragma unroll
        for (int a = 0; a < 2; a++) {
            const float inv0 = __fdividef(1.f, lsum[a][0]);
            const float inv1 = __fdividef(1.f, lsum[a][1]);
            int row0 = jr + a * 16 + r;
            const size_t grow0 = base_i + (size_t)row0 * CZ + h * HD;
            const size_t grow1 = grow0 + 8 * CZ;
#pragma unroll
            for (int ntd = 0; ntd < 4; ntd++) {
                int col = ntd * 8 + c2;
                float2 g0 = unpack_h2(__ldg((const u32*)(g_Gh + grow0 + col)));
                float2 g1 = unpack_h2(__ldg((const u32*)(g_Gh + grow1 + col)));
                u32 o0 = pack_h2(oacc[a][ntd][0] * inv0 * g0.x,
                                 oacc[a][ntd][1] * inv0 * g0.y);
                u32 o1 = pack_h2(oacc[a][ntd][2] * inv1 * g1.x,
                                 oacc[a][ntd][3] * inv1 * g1.y);
                *(u32*)(sm + F_AV + (u32)(row0 * TSTRIDE + h * HD + col) * 2)       = o0;
                *(u32*)(sm + F_AV + (u32)((row0 + 8) * TSTRIDE + h * HD + col) * 2) = o1;
            }
        }
        __syncthreads();
    }

    // ---- output projection from smem AV (256 rows x 128) ----
    const int wr = wid & 1, wc = wid >> 1;
    const u32 bBase = sb + F_WO +
        (u32)((wc * 32 + ((i_ >> 1) << 3) + r_) * TSTRIDE + ((i_ & 1) << 3)) * 2;
    const int g = lane >> 2, tig = lane & 3;

#pragma unroll
    for (int half = 0; half < 2; half++) {
        const u32 aBase = sb + F_AV +
            (u32)((half * 128 + wr * 64 + ((i_ & 1) << 3) + r_) * TSTRIDE + ((i_ >> 1) << 3)) * 2;
        float acc[16][4];
#pragma unroll
        for (int t = 0; t < 16; t++)
#pragma unroll
            for (int v = 0; v < 4; v++) acc[t][v] = 0.f;

        gemm_warp64(acc, aBase, bBase);

#pragma unroll
        for (int ai = 0; ai < 4; ai++) {
            size_t rowA = (size_t)bi * NSEQ + half * 128 + wr * 64 + ai * 16 + g;
            size_t rowB = rowA + 8;
#pragma unroll
            for (int ni = 0; ni < 4; ni++) {
                int col = wc * 32 + ni * 8 + tig * 2;
                float2 bov = __ldg((const float2*)(bo_ + col));
                float* a = acc[ai * 4 + ni];
                *(float2*)(out + rowA * CZ + col) = make_float2(a[0] + bov.x, a[1] + bov.y);
                *(float2*)(out + rowB * CZ + col) = make_float2(a[2] + bov.x, a[3] + bov.y);
            }
        }
    }
}

// ---------------------------------------------------------------------------
extern "C" void kernel_launch(void* const* d_in, const int* in_sizes, int n_in,
                              void* d_out, int out_size)
{
    const float* x     = (const float*)d_in[0];
    const float* gamma = (const float*)d_in[1];
    const float* beta  = (const float*)d_in[2];
    const float* Wq    = (const float*)d_in[3];
    const float* Wk    = (const float*)d_in[4];
    const float* Wv    = (const float*)d_in[5];
    const float* Wb    = (const float*)d_in[6];
    const float* Wg    = (const float*)d_in[7];
    const float* bg    = (const float*)d_in[8];
    const float* Wo    = (const float*)d_in[9];
    const float* bo    = (const float*)d_in[10];
    float* out = (float*)d_out;

    cudaFuncSetAttribute(lnproj_mma,     cudaFuncAttributeMaxDynamicSharedMemorySize, LNP_SMEM);
    cudaFuncSetAttribute(attn_out_fused, cudaFuncAttributeMaxDynamicSharedMemorySize, F_SMEM);

    dim3 gw(5, 16);
    wtransform<<<gw, 256>>>(Wq, Wk, Wv, Wg, Wo);
    lnproj_mma<<<RTOT / 128, 256, LNP_SMEM>>>(x, gamma, beta, Wb, bg);
    attn_out_fused<<<NSEQ, 256, F_SMEM>>>(bo, out);
}

// round 16
// speedup vs baseline: 1.1176x; 1.0121x over previous
#include <cuda_runtime.h>
#include <cuda_fp16.h>
#include <math.h>

#define NSEQ 256
#define CZ   128
#define NH   4
#define HD   32
#define RTOT (NSEQ * NSEQ)

typedef unsigned int u32;
typedef unsigned long long u64;

// ---------------- global scratch ----------------
__device__ __half g_Qh[(size_t)RTOT * CZ];    // pre-scaled by log2e/sqrt(32)
__device__ __half g_Kh[(size_t)RTOT * CZ];
__device__ __half g_Vh[(size_t)RTOT * CZ];
__device__ __half g_Gh[(size_t)RTOT * CZ];    // gate, fp16
__device__ __half g_BiasT[(size_t)NH * RTOT]; // fp16, pre-scaled by log2e
__device__ __half g_Wt[5][CZ * CZ];

// ---------------- helpers ----------------
__device__ __forceinline__ u32 smem_u32(const void* p) {
    u32 a;
    asm("{ .reg .u64 t; cvta.to.shared.u64 t, %1; cvt.u32.u64 %0, t; }" : "=r"(a) : "l"(p));
    return a;
}
__device__ __forceinline__ void ldsm_x4(u32* r, u32 addr) {
    asm volatile("ldmatrix.sync.aligned.m8n8.x4.shared.b16 {%0,%1,%2,%3}, [%4];"
        : "=r"(r[0]), "=r"(r[1]), "=r"(r[2]), "=r"(r[3]) : "r"(addr));
}
__device__ __forceinline__ void ldsm_x4_t(u32* r, u32 addr) {
    asm volatile("ldmatrix.sync.aligned.m8n8.x4.trans.shared.b16 {%0,%1,%2,%3}, [%4];"
        : "=r"(r[0]), "=r"(r[1]), "=r"(r[2]), "=r"(r[3]) : "r"(addr));
}
__device__ __forceinline__ void mma_f16(float* d, const u32* a, const u32* b) {
    asm volatile("mma.sync.aligned.m16n8k16.row.col.f32.f16.f16.f32 "
        "{%0,%1,%2,%3}, {%4,%5,%6,%7}, {%8,%9}, {%0,%1,%2,%3};"
        : "+f"(d[0]), "+f"(d[1]), "+f"(d[2]), "+f"(d[3])
        : "r"(a[0]), "r"(a[1]), "r"(a[2]), "r"(a[3]), "r"(b[0]), "r"(b[1]));
}
__device__ __forceinline__ u32 pack_h2(float x, float y) {
    __half2 t;
    t.x = __float2half_rn(x);
    t.y = __float2half_rn(y);
    return *(u32*)&t;
}
__device__ __forceinline__ float2 unpack_h2(u32 v) {
    __half2 t = *(__half2*)&v;
    return __half22float2(t);
}
__device__ __forceinline__ void cp16(u32 dst, const void* src) {
    u64 g;
    asm("cvta.to.global.u64 %0, %1;" : "=l"(g) : "l"(src));
    asm volatile("cp.async.ca.shared.global [%0], [%1], 16;" :: "r"(dst), "l"(g));
}
#define CP_COMMIT() asm volatile("cp.async.commit_group;")
#define CP_WAIT(n)  asm volatile("cp.async.wait_group %0;" :: "n"(n))

#define TSTRIDE 136
#define TBUF    34816

// lnproj smem
#define LNP_SA   0
#define LNP_SB0  34816
#define LNP_SB1  69632
#define LNP_XS   34816
#define LNP_WB   104448
#define LNP_SMEM 106496

// fused attn+outproj smem (single KV buffer -> 2 CTA/SM)
#define KSTR   40
#define KVBUF  20480
#define F_KV   0                     // K | V (40960)
#define F_AV   40960                 // 256 * 136 * 2 = 69632 / 2 rows? no: full 256 rows
#define F_WO   (40960 + 69632)       // 110592
#define F_SMEM (40960 + 69632 + 34816)  // 145408 -- too big? NO: see below

// AV must hold 256 rows x 136 = 69632. 40960 + 69632 + 34816 = 145408 > 113.5K.
// Fix: store AV at stride 136 but only 128 cols used -> cannot shrink rows.
// Instead: overlap AV with nothing; shrink by using KV buffer region for Wo after
// last head? Simpler: AV stride 132 (128 cols + 4 pad) = 256*132*2 = 67584.
// 40960 + 67584 + 34816 = 143360. Still too big.
// Real fix: keep AV in smem but stage Wo into the KV buffer after head 3
// (KV no longer needed). Layout: KV(40960) | AV(69632) = 110592 total. Wo -> KV region.
#undef F_AV
#undef F_WO
#undef F_SMEM
#define F_AV   40960
#define F_WO   0                     // reuse KV buffer for Wo after last head
#define F_SMEM 110592

// ---------------------------------------------------------------------------
// Kernel 0: transpose weights -> fp16. Grid (5, 16), 1 float4/thread.
// ---------------------------------------------------------------------------
__global__ void wtransform(const float* __restrict__ Wq, const float* __restrict__ Wk,
                           const float* __restrict__ Wv, const float* __restrict__ Wg,
                           const float* __restrict__ Wo)
{
    const float* W = (blockIdx.x == 0) ? Wq : (blockIdx.x == 1) ? Wk :
                     (blockIdx.x == 2) ? Wv : (blockIdx.x == 3) ? Wg : Wo;
    __half* H = g_Wt[blockIdx.x];
    int e4 = blockIdx.y * 256 + threadIdx.x;
    float4 v = ((const float4*)W)[e4];
    int e = e4 * 4;
    int c = e >> 7, n = e & 127;
    H[(n + 0) * 128 + c] = __float2half_rn(v.x);
    H[(n + 1) * 128 + c] = __float2half_rn(v.y);
    H[(n + 2) * 128 + c] = __float2half_rn(v.z);
    H[(n + 3) * 128 + c] = __float2half_rn(v.w);
}

// ---------------------------------------------------------------------------
// 64x32 warp-tile GEMM mainloop
// ---------------------------------------------------------------------------
__device__ __forceinline__ void gemm_warp64(float acc[16][4], u32 aBase, u32 bBase)
{
#pragma unroll
    for (int ks = 0; ks < 8; ks++) {
        u32 a0[4], a1[4], a2[4], a3[4], b0[4], b1[4];
        ldsm_x4(a0, aBase + ks * 32);
        ldsm_x4(a1, aBase + (u32)(16 * TSTRIDE) * 2 + ks * 32);
        ldsm_x4(a2, aBase + (u32)(32 * TSTRIDE) * 2 + ks * 32);
        ldsm_x4(a3, aBase + (u32)(48 * TSTRIDE) * 2 + ks * 32);
        ldsm_x4(b0, bBase + ks * 32);
        ldsm_x4(b1, bBase + (u32)(16 * TSTRIDE) * 2 + ks * 32);
        mma_f16(acc[0],  a0, b0); mma_f16(acc[1],  a0, b0 + 2);
        mma_f16(acc[2],  a0, b1); mma_f16(acc[3],  a0, b1 + 2);
        mma_f16(acc[4],  a1, b0); mma_f16(acc[5],  a1, b0 + 2);
        mma_f16(acc[6],  a1, b1); mma_f16(acc[7],  a1, b1 + 2);
        mma_f16(acc[8],  a2, b0); mma_f16(acc[9],  a2, b0 + 2);
        mma_f16(acc[10], a2, b1); mma_f16(acc[11], a2, b1 + 2);
        mma_f16(acc[12], a3, b0); mma_f16(acc[13], a3, b0 + 2);
        mma_f16(acc[14], a3, b1); mma_f16(acc[15], a3, b1 + 2);
    }
}

__device__ __forceinline__ void cp_weights(u32 sb, u32 bufOff, int m, int tid, int nthr)
{
    for (int e = tid; e < 2048; e += nthr) {
        int n = e >> 4, ch = e & 15;
        const __half* src = g_Wt[m] + n * 128 + ch * 8;
        cp16(sb + bufOff + (u32)(n * TSTRIDE + ch * 8) * 2, src);
    }
}

// ---------------------------------------------------------------------------
// Kernel 1: LN (fp16 direct to A-tile) + bias via MMA + 4 projections (1-term)
// ---------------------------------------------------------------------------
__global__ __launch_bounds__(256, 2) void lnproj_mma(const float* __restrict__ x,
                                                     const float* __restrict__ gamma,
                                                     const float* __restrict__ beta,
                                                     const float* __restrict__ Wb,
                                                     const float* __restrict__ bg)
{
    extern __shared__ char sm[];
    const u32 sb = smem_u32(sm);
    const int tid = threadIdx.x, wid = tid >> 5, lane = tid & 31;
    const int wr = wid & 1, wc = wid >> 1;
    const size_t r0 = (size_t)blockIdx.x * 128;
    float* xs = (float*)(sm + LNP_XS);
    __half* sWbh = (__half*)(sm + LNP_WB);
    const float LOG2E = 1.4426950408889634f;

    const float4* xg = (const float4*)(x + r0 * CZ);
    for (int i = tid; i < 4096; i += 256) {
        float4 v = xg[i];
        int row = i >> 5, c = (i & 31) << 2;
        float* d = xs + row * 129 + c;
        d[0] = v.x; d[1] = v.y; d[2] = v.z; d[3] = v.w;
    }
    for (int e = tid; e < 1024; e += 256) {
        int c = e >> 3, h = e & 7;
        float v = (h < 4) ? __ldg(Wb + c * 4 + h) : 0.f;
        sWbh[((c >> 1) * 8 + h) * 2 + (c & 1)] = __float2half_rn(v);
    }
    __syncthreads();

    // LayerNorm: 2 threads per row; write fp16 directly into A-tile
    {
        int row = tid >> 1, sub = tid & 1;
        float* rp = xs + row * 129;
        float s = 0.f, s2 = 0.f;
#pragma unroll
        for (int c = sub * 64; c < sub * 64 + 64; c++) { float v = rp[c]; s += v; s2 += v * v; }
        s  += __shfl_xor_sync(0xFFFFFFFF, s, 1);
        s2 += __shfl_xor_sync(0xFFFFFFFF, s2, 1);
        float mu  = s * (1.f / 128.f);
        float var = s2 * (1.f / 128.f) - mu * mu;
        float inv = rsqrtf(var + 1e-5f);
#pragma unroll
        for (int c = sub * 64; c < sub * 64 + 64; c += 2) {
            float v0 = (rp[c]     - mu) * inv * __ldg(gamma + c)     + __ldg(beta + c);
            float v1 = (rp[c + 1] - mu) * inv * __ldg(gamma + c + 1) + __ldg(beta + c + 1);
            *(u32*)(sm + LNP_SA + (u32)(row * TSTRIDE + c) * 2) = pack_h2(v0, v1);
        }
    }
    __syncthreads();

    cp_weights(sb, LNP_SB0, 0, tid, 256);
    CP_COMMIT();

    const int i_ = lane >> 3, r_ = lane & 7;
    const u32 aBase = sb + LNP_SA +
        (u32)((wr * 64 + ((i_ & 1) << 3) + r_) * TSTRIDE + ((i_ >> 1) << 3)) * 2;
    const u32 bOffW = (u32)((wc * 32 + ((i_ >> 1) << 3) + r_) * TSTRIDE + ((i_ & 1) << 3)) * 2;
    const int g = lane >> 2, tig = lane & 3;

    // bias projection via MMA (overlaps m=0 weight copy)
    {
        const u32 aB = sb + LNP_SA +
            (u32)((wid * 16 + ((i_ & 1) << 3) + r_) * TSTRIDE + ((i_ >> 1) << 3)) * 2;
        const u32* wb32 = (const u32*)sWbh;
        float dacc[4] = {0.f, 0.f, 0.f, 0.f};
#pragma unroll
        for (int ks = 0; ks < 8; ks++) {
            u32 a[4], b[2];
            ldsm_x4(a, aB + ks * 32);
            b[0] = wb32[(ks * 8 + tig) * 8 + g];
            b[1] = wb32[(ks * 8 + 4 + tig) * 8 + g];
            mma_f16(dacc, a, b);
        }
        int row = wid * 16 + g;
        int col0 = tig * 2;
        if (col0 < NH) {
            g_BiasT[(size_t)col0 * RTOT + r0 + row]           = __float2half_rn(dacc[0] * LOG2E);
            g_BiasT[(size_t)(col0 + 1) * RTOT + r0 + row]     = __float2half_rn(dacc[1] * LOG2E);
            g_BiasT[(size_t)col0 * RTOT + r0 + row + 8]       = __float2half_rn(dacc[2] * LOG2E);
            g_BiasT[(size_t)(col0 + 1) * RTOT + r0 + row + 8] = __float2half_rn(dacc[3] * LOG2E);
        }
    }

#pragma unroll
    for (int m = 0; m < 4; m++) {
        if (m < 3) { cp_weights(sb, (m & 1) ? LNP_SB0 : LNP_SB1, m + 1, tid, 256); CP_COMMIT(); }
        if (m < 3) { CP_WAIT(1); } else { CP_WAIT(0); }
        __syncthreads();

        const u32 bufOff = (m & 1) ? LNP_SB1 : LNP_SB0;
        float acc[16][4];
#pragma unroll
        for (int t = 0; t < 16; t++)
#pragma unroll
            for (int v = 0; v < 4; v++) acc[t][v] = 0.f;

        gemm_warp64(acc, aBase, sb + bufOff + bOffW);

        if (m == 0) {
            const float qs = 0.17677669529663689f * 1.4426950408889634f;
#pragma unroll
            for (int ai = 0; ai < 4; ai++) {
                size_t rowA = r0 + wr * 64 + ai * 16 + g;
                size_t rowB = rowA + 8;
#pragma unroll
                for (int ni = 0; ni < 4; ni++) {
                    int col = wc * 32 + ni * 8 + tig * 2;
                    float* a = acc[ai * 4 + ni];
                    *(u32*)(g_Qh + rowA * CZ + col) = pack_h2(a[0] * qs, a[1] * qs);
                    *(u32*)(g_Qh + rowB * CZ + col) = pack_h2(a[2] * qs, a[3] * qs);
                }
            }
        } else if (m < 3) {
            __half* O = (m == 1) ? g_Kh : g_Vh;
#pragma unroll
            for (int ai = 0; ai < 4; ai++) {
                size_t rowA = r0 + wr * 64 + ai * 16 + g;
                size_t rowB = rowA + 8;
#pragma unroll
                for (int ni = 0; ni < 4; ni++) {
                    int col = wc * 32 + ni * 8 + tig * 2;
                    float* a = acc[ai * 4 + ni];
                    *(u32*)(O + rowA * CZ + col) = pack_h2(a[0], a[1]);
                    *(u32*)(O + rowB * CZ + col) = pack_h2(a[2], a[3]);
                }
            }
        } else {
#pragma unroll
            for (int ai = 0; ai < 4; ai++) {
                size_t rowA = r0 + wr * 64 + ai * 16 + g;
                size_t rowB = rowA + 8;
#pragma unroll
                for (int ni = 0; ni < 4; ni++) {
                    int col = wc * 32 + ni * 8 + tig * 2;
                    float2 bgv = __ldg((const float2*)(bg + col));
                    float* a = acc[ai * 4 + ni];
                    float gA0 = 1.f / (1.f + __expf(-(a[0] + bgv.x)));
                    float gA1 = 1.f / (1.f + __expf(-(a[1] + bgv.y)));
                    float gB0 = 1.f / (1.f + __expf(-(a[2] + bgv.x)));
                    float gB1 = 1.f / (1.f + __expf(-(a[3] + bgv.y)));
                    *(u32*)(g_Gh + rowA * CZ + col) = pack_h2(gA0, gA1);
                    *(u32*)(g_Gh + rowB * CZ + col) = pack_h2(gB0, gB1);
                }
            }
        }
        __syncthreads();
    }
}

// ---------------------------------------------------------------------------
// Kernel 2 (fused): attention over 4 heads (single KV buffer, 2 CTA/SM)
// + output projection from smem (Wo staged into KV region after last head).
// Grid 256 (one CTA per i). 8 warps x 32 j.
// ---------------------------------------------------------------------------
__device__ __forceinline__ void stage_kv(u32 sb, size_t base_i, int h, int tid)
{
    for (int e = tid; e < 2048; e += 256) {
        int buf = e >> 10, rem = e & 1023, k = rem >> 2, ch = rem & 3;
        const __half* src = ((buf == 0) ? g_Kh : g_Vh)
            + base_i + (size_t)k * CZ + h * HD + ch * 8;
        cp16(sb + F_KV + (u32)buf * KVBUF + (u32)(k * KSTR + ch * 8) * 2, src);
    }
}

__global__ __launch_bounds__(256, 2) void attn_out_fused(const float* __restrict__ bo_,
                                                         float* __restrict__ out)
{
    extern __shared__ char sm[];
    const u32 sb = smem_u32(sm);
    const int tid = threadIdx.x, wid = tid >> 5, lane = tid & 31;
    const int bi = blockIdx.x;
    const size_t base_i = (size_t)bi * NSEQ * CZ;

    stage_kv(sb, base_i, 0, tid);
    CP_COMMIT();

    const int jr = wid * 32;
    const int r  = lane >> 2, c2 = (lane & 3) << 1;
    const int i_ = lane >> 3, r_ = lane & 7;
    const int brow = ((i_ >> 1) << 3) + r_;
    const int bcol = (i_ & 1) << 3;
    const int vsel = lane >> 3, vrow = lane & 7;
    const u32 vOff = (u32)(((vsel & 1) * 8 + vrow) * KSTR + ((vsel >> 1) << 3)) * 2;

    for (int h = 0; h < NH; h++) {
        // Q fragments first (independent of pending cp.async)
        u32 qh[2][2][4];
#pragma unroll
        for (int a = 0; a < 2; a++)
#pragma unroll
            for (int ks = 0; ks < 2; ks++)
#pragma unroll
                for (int reg = 0; reg < 4; reg++) {
                    int row = jr + a * 16 + r + (reg & 1) * 8;
                    int col = ks * 16 + c2 + ((reg >> 1) << 3);
                    qh[a][ks][reg] = *(const u32*)(g_Qh + base_i + (size_t)row * CZ + h * HD + col);
                }

        CP_WAIT(0);
        __syncthreads();

        float oacc[2][4][4];
#pragma unroll
        for (int a = 0; a < 2; a++)
#pragma unroll
            for (int t = 0; t < 4; t++)
#pragma unroll
                for (int v = 0; v < 4; v++) oacc[a][t][v] = 0.f;
        float lsum[2][2] = {{0.f, 0.f}, {0.f, 0.f}};

        const __half* biasH = g_BiasT + (size_t)h * RTOT;

        for (int kc = 0; kc < 8; kc++) {
            float sacc[2][4][4];
#pragma unroll
            for (int a = 0; a < 2; a++)
#pragma unroll
                for (int t = 0; t < 4; t++)
#pragma unroll
                    for (int v = 0; v < 4; v++) sacc[a][t][v] = 0.f;

#pragma unroll
            for (int ks = 0; ks < 2; ks++) {
                u32 k0[4], k1[4];
                u32 ka = sb + F_KV + (u32)((kc * 32 + brow) * KSTR + ks * 16 + bcol) * 2;
                ldsm_x4(k0, ka);
                ldsm_x4(k1, ka + (u32)(16 * KSTR) * 2);
#pragma unroll
                for (int a = 0; a < 2; a++) {
                    mma_f16(sacc[a][0], qh[a][ks], k0);
                    mma_f16(sacc[a][1], qh[a][ks], k0 + 2);
                    mma_f16(sacc[a][2], qh[a][ks], k1);
                    mma_f16(sacc[a][3], qh[a][ks], k1 + 2);
                }
            }

#pragma unroll
            for (int a = 0; a < 2; a++) {
                const __half* b0p = biasH + (size_t)(jr + a * 16 + r) * NSEQ;
                const __half* b1p = b0p + 8 * NSEQ;
#pragma unroll
                for (int nt = 0; nt < 4; nt++) {
                    int kcol = kc * 32 + nt * 8 + c2;
                    float2 b0 = unpack_h2(__ldg((const u32*)(b0p + kcol)));
                    float2 b1 = unpack_h2(__ldg((const u32*)(b1p + kcol)));
                    float p00 = exp2f(sacc[a][nt][0] + b0.x);
                    float p01 = exp2f(sacc[a][nt][1] + b0.y);
                    float p10 = exp2f(sacc[a][nt][2] + b1.x);
                    float p11 = exp2f(sacc[a][nt][3] + b1.y);
                    sacc[a][nt][0] = p00; sacc[a][nt][1] = p01;
                    sacc[a][nt][2] = p10; sacc[a][nt][3] = p11;
                    lsum[a][0] += p00 + p01;
                    lsum[a][1] += p10 + p11;
                }
            }

#pragma unroll
            for (int ks2 = 0; ks2 < 2; ks2++) {
                u32 va = sb + F_KV + KVBUF + (u32)((kc * 32 + ks2 * 16) * KSTR) * 2 + vOff;
                u32 vh[8];
                ldsm_x4_t(vh,     va);
                ldsm_x4_t(vh + 4, va + 32);
#pragma unroll
                for (int a = 0; a < 2; a++) {
                    u32 phi[4];
                    const float* s0 = sacc[a][2 * ks2];
                    const float* s1 = sacc[a][2 * ks2 + 1];
                    phi[0] = pack_h2(s0[0], s0[1]);
                    phi[1] = pack_h2(s0[2], s0[3]);
                    phi[2] = pack_h2(s1[0], s1[1]);
                    phi[3] = pack_h2(s1[2], s1[3]);
#pragma unroll
                    for (int ntd = 0; ntd < 4; ntd++)
                        mma_f16(oacc[a][ntd], phi, vh + 2 * ntd);
                }
            }
        }

#pragma unroll
        for (int a = 0; a < 2; a++)
#pragma unroll
            for (int c = 0; c < 2; c++) {
                lsum[a][c] += __shfl_xor_sync(0xFFFFFFFF, lsum[a][c], 1);
                lsum[a][c] += __shfl_xor_sync(0xFFFFFFFF, lsum[a][c], 2);
            }

        __syncthreads();   // all warps done reading KV before restage/Wo

        if (h < 3)      { stage_kv(sb, base_i, h + 1, tid); CP_COMMIT(); }
        else            { cp_weights(sb, F_WO, 4, tid, 256); CP_COMMIT(); }

#pragma unroll
        for (int a = 0; a < 2; a++) {
            const float inv0 = __fdividef(1.f, lsum[a][0]);
            const float inv1 = __fdividef(1.f, lsum[a][1]);
            int row0 = jr + a * 16 + r;
            const size_t grow0 = base_i + (size_t)row0 * CZ + h * HD;
            const size_t grow1 = grow0 + 8 * CZ;
#pragma unroll
            for (int ntd = 0; ntd < 4; ntd++) {
                int col = ntd * 8 + c2;
                float2 g0 = unpack_h2(__ldg((const u32*)(g_Gh + grow0 + col)));
                float2 g1 = unpack_h2(__ldg((const u32*)(g_Gh + grow1 + col)));
                u32 o0 = pack_h2(oacc[a][ntd][0] * inv0 * g0.x,
                                 oacc[a][ntd][1] * inv0 * g0.y);
                u32 o1 = pack_h2(oacc[a][ntd][2] * inv1 * g1.x,
                                 oacc[a][ntd][3] * inv1 * g1.y);
                *(u32*)(sm + F_AV + (u32)(row0 * TSTRIDE + h * HD + col) * 2)       = o0;
                *(u32*)(sm + F_AV + (u32)((row0 + 8) * TSTRIDE + h * HD + col) * 2) = o1;
            }
        }
    }

    CP_WAIT(0);        // Wo staged
    __syncthreads();   // AV writes visible

    // ---- output projection from smem AV (256 rows x 128) ----
    const int wr = wid & 1, wc = wid >> 1;
    const u32 bBase = sb + F_WO +
        (u32)((wc * 32 + ((i_ >> 1) << 3) + r_) * TSTRIDE + ((i_ & 1) << 3)) * 2;
    const int g = lane >> 2, tig = lane & 3;

#pragma unroll
    for (int half = 0; half < 2; half++) {
        const u32 aBase = sb + F_AV +
            (u32)((half * 128 + wr * 64 + ((i_ & 1) << 3) + r_) * TSTRIDE + ((i_ >> 1) << 3)) * 2;
        float acc[16][4];
#pragma unroll
        for (int t = 0; t < 16; t++)
#pragma unroll
            for (int v = 0; v < 4; v++) acc[t][v] = 0.f;

        gemm_warp64(acc, aBase, bBase);

#pragma unroll
        for (int ai = 0; ai < 4; ai++) {
            size_t rowA = (size_t)bi * NSEQ + half * 128 + wr * 64 + ai * 16 + g;
            size_t rowB = rowA + 8;
#pragma unroll
            for (int ni = 0; ni < 4; ni++) {
                int col = wc * 32 + ni * 8 + tig * 2;
                float2 bov = __ldg((const float2*)(bo_ + col));
                float* a = acc[ai * 4 + ni];
                *(float2*)(out + rowA * CZ + col) = make_float2(a[0] + bov.x, a[1] + bov.y);
                *(float2*)(out + rowB * CZ + col) = make_float2(a[2] + bov.x, a[3] + bov.y);
            }
        }
    }
}

// ---------------------------------------------------------------------------
extern "C" void kernel_launch(void* const* d_in, const int* in_sizes, int n_in,
                              void* d_out, int out_size)
{
    const float* x     = (const float*)d_in[0];
    const float* gamma = (const float*)d_in[1];
    const float* beta  = (const float*)d_in[2];
    const float* Wq    = (const float*)d_in[3];
    const float* Wk    = (const float*)d_in[4];
    const float* Wv    = (const float*)d_in[5];
    const float* Wb    = (const float*)d_in[6];
    const float* Wg    = (const float*)d_in[7];
    const float* bg    = (const float*)d_in[8];
    const float* Wo    = (const float*)d_in[9];
    const float* bo    = (const float*)d_in[10];
    float* out = (float*)d_out;

    cudaFuncSetAttribute(lnproj_mma,     cudaFuncAttributeMaxDynamicSharedMemorySize, LNP_SMEM);
    cudaFuncSetAttribute(attn_out_fused, cudaFuncAttributeMaxDynamicSharedMemorySize, F_SMEM);

    dim3 gw(5, 16);
    wtransform<<<gw, 256>>>(Wq, Wk, Wv, Wg, Wo);
    lnproj_mma<<<RTOT / 128, 256, LNP_SMEM>>>(x, gamma, beta, Wb, bg);
    attn_out_fused<<<NSEQ, 256, F_SMEM>>>(bo, out);
}